// round 12
// baseline (speedup 1.0000x reference)
#include <cuda_runtime.h>
#include <cuda_fp16.h>
#include <math.h>
#include <stdint.h>

// ---------------- problem constants ----------------
#define LNUM  6
#define D     1024
#define H     16
#define DKH   64
#define FFD   4096
#define TT    1024
#define BATCH 2
#define NTOK  2048
#define D3    3072
#define D2    2048
#define ATT_SCALE 0.125f
#define SCL   0.015625f        // 2^-6
#define SCLI  64.0f            // 2^6

#define SWZ(o) ((o) ^ (((o) >> 3) & 0x70))

// ---------------- scratch (device globals; no allocs allowed) ----------------
__device__ float g_x   [NTOK*D];     // residual stream (f32)
__device__ float g_qkv [NTOK*D3];
__device__ float g_gate[NTOK*D3];
__device__ __half g_chi[NTOK*D2],  g_clo[NTOK*D2];   // concat [x,y] hi / A2
__device__ __half g_lhi[NTOK*D],   g_llo[NTOK*D];    // LN output hi / A2
__device__ __half g_phi[NTOK*D],   g_plo[NTOK*D];    // attn output hi / A2
__device__ __half g_fhi[NTOK*FFD], g_flo[NTOK*FFD];  // FF hidden hi / A2
__device__ __half g_xhi[NTOK*D],   g_xlo[NTOK*D];    // input x split
__device__ __half wb_in_hi [D*D],        wb_in_lo [D*D];
__device__ __half wb_qkv_hi[LNUM*D3*D],  wb_qkv_lo[LNUM*D3*D];
__device__ __half wb_out_hi[LNUM*D*D],   wb_out_lo[LNUM*D*D];
__device__ __half wb_f1_hi [LNUM*FFD*D], wb_f1_lo [LNUM*FFD*D];
__device__ __half wb_f2_hi [LNUM*D*FFD], wb_f2_lo [LNUM*D*FFD];
__device__ __half wb_g1_hi [LNUM*D3*D2], wb_g1_lo [LNUM*D3*D2];
__device__ __half wb_g2_hi [LNUM*D3*D2], wb_g2_lo [LNUM*D3*D2];

// ---------------- PTX helpers (portable: sm_80-level) ----------------
__device__ __forceinline__ uint32_t smem_u32(const void* p) {
    uint32_t a;
    asm("{ .reg .u64 t; cvta.to.shared.u64 t, %1; cvt.u32.u64 %0, t; }" : "=r"(a) : "l"(p));
    return a;
}
__device__ __forceinline__ void cp16(uint32_t d, const void* g) {
    asm volatile("cp.async.cg.shared.global [%0], [%1], 16;" :: "r"(d), "l"(g));
}
__device__ __forceinline__ void ldm_x4(uint32_t* f, uint32_t addr) {
    asm volatile("ldmatrix.sync.aligned.m8n8.x4.shared.b16 {%0,%1,%2,%3}, [%4];"
                 : "=r"(f[0]), "=r"(f[1]), "=r"(f[2]), "=r"(f[3]) : "r"(addr));
}
__device__ __forceinline__ void mma16816(float* c, const uint32_t* a, uint32_t b0, uint32_t b1) {
    asm volatile(
        "mma.sync.aligned.m16n8k16.row.col.f32.f16.f16.f32 "
        "{%0,%1,%2,%3}, {%4,%5,%6,%7}, {%8,%9}, {%0,%1,%2,%3};"
        : "+f"(c[0]), "+f"(c[1]), "+f"(c[2]), "+f"(c[3])
        : "r"(a[0]), "r"(a[1]), "r"(a[2]), "r"(a[3]), "r"(b0), "r"(b1));
}
__device__ __forceinline__ float gelu_exact(float v) { return v * normcdff(v); }

// Activation split: hi = fp16(v); A2 = fp16((v - hi) + hi*2^-6)
__device__ __forceinline__ void split_act(float v, __half& h, __half& a2) {
    h = __float2half_rn(v);
    float lo = v - __half2float(h);
    a2 = __float2half_rn(fmaf(__half2float(h), SCL, lo));
}
// Weight split: hi = fp16(w); W2 = fp16(hi + (w - hi)*2^6)
__device__ __forceinline__ void split_wgt(float w, __half& h, __half& w2) {
    h = __float2half_rn(w);
    float lo = w - __half2float(h);
    w2 = __float2half_rn(fmaf(lo, SCLI, __half2float(h)));
}
// Final combine: C = acc1*(1 - 2^-6) + acc2
__device__ __forceinline__ float combine(float a1, float a2) {
    return fmaf(a1, 1.0f - SCL, a2);
}

// ---------------- fp16 2-MMA GEMM (persistent, 3-stage, wait_group 1) --------
#define STAGE_B 65536
#define NSTAGE  3
#define SMEM_BYTES (NSTAGE*STAGE_B)

__global__ __launch_bounds__(256)
void gemm_mma(const __half* __restrict__ Ahi, const __half* __restrict__ A2p,
              int lda,
              const __half* __restrict__ Whi, const __half* __restrict__ W2p,
              const float* __restrict__ bias,
              float* __restrict__ Cf,
              __half* __restrict__ Chi, __half* __restrict__ Clo,
              int ldc, int K, int mode, int gx, int ntiles)
{
    extern __shared__ char smem[];
    const uint32_t sb = smem_u32(smem);
    const int tid  = threadIdx.x;
    const int wid  = tid >> 5;
    const int lane = tid & 31;
    const int wm   = wid >> 1;
    const int wn   = wid & 1;

    const int lr   = lane & 15;
    const int koff = (lane >> 4) << 4;
    uint32_t roffA[2], rxA[2], roffB[4], rxB[4];
#pragma unroll
    for (int i = 0; i < 2; i++) {
        int r = wm * 32 + i * 16 + lr;
        roffA[i] = r * 128; rxA[i] = (r & 7) << 4;
    }
#pragma unroll
    for (int j = 0; j < 4; j++) {
        int r = wn * 64 + j * 16 + lr;
        roffB[j] = r * 128; rxB[j] = (r & 7) << 4;
    }

    const int nch = K / 64;
    const int ldr = tid >> 3, ldc4 = tid & 7;

    // issue chunk (global index gc counts chunks across the whole tile walk)
    auto issue = [&](int tt, int cc, int stage) {
        const int r0 = (tt / gx) * 128;
        const int c0 = (tt % gx) * 128;
        const int kbase = cc * 64;
        const uint32_t st = sb + stage * STAGE_B;
#pragma unroll
        for (int i = 0; i < 4; i++) {
            int r = ldr + i * 32;
            uint32_t off = SWZ((uint32_t)(r * 128 + ldc4 * 16));
            size_t sa = (size_t)(r0 + r) * lda + kbase + ldc4 * 8;
            size_t sw = (size_t)(c0 + r) * K   + kbase + ldc4 * 8;
            cp16(st +         off, Ahi + sa);
            cp16(st + 16384 + off, A2p + sa);
            cp16(st + 32768 + off, Whi + sw);
            cp16(st + 49152 + off, W2p + sw);
        }
        asm volatile("cp.async.commit_group;");
    };

    const int grid = (int)gridDim.x;
    // chunk walk: linear global counter over (tile, chunk) pairs this CTA owns
    const int mytiles = (ntiles - (int)blockIdx.x + grid - 1) / grid;
    const long totch = (long)mytiles * nch;

    auto chunk_of = [&](long gcc, int& tt, int& cc) {
        int ti = (int)(gcc / nch);
        tt = (int)blockIdx.x + ti * grid;
        cc = (int)(gcc % nch);
    };

    // prologue: fill pipeline with 2 chunks
    {
        int tt, cc;
        if (totch > 0) { chunk_of(0, tt, cc); issue(tt, cc, 0); }
        if (totch > 1) { chunk_of(1, tt, cc); issue(tt, cc, 1); }
    }

    long gc = 0;
    for (int t = blockIdx.x; t < ntiles; t += grid) {
        const int row0 = (t / gx) * 128;
        const int col0 = (t % gx) * 128;

        float acc1[2][8][4], acc2[2][8][4];
#pragma unroll
        for (int i = 0; i < 2; i++)
#pragma unroll
            for (int g = 0; g < 8; g++)
#pragma unroll
                for (int q = 0; q < 4; q++) { acc1[i][g][q] = 0.f; acc2[i][g][q] = 0.f; }

        for (int cc = 0; cc < nch; cc++, gc++) {
            asm volatile("cp.async.wait_group 1;");   // chunk gc arrived
            __syncthreads();
            if (gc + 2 < totch) {
                int ntt, ncc; chunk_of(gc + 2, ntt, ncc);
                issue(ntt, ncc, (int)((gc + 2) % NSTAGE));
            }

            const uint32_t AH = sb + (uint32_t)(gc % NSTAGE) * STAGE_B;
            const uint32_t AL = AH + 16384;
            const uint32_t WHs = AH + 32768;
            const uint32_t WLs = AH + 49152;
#pragma unroll
            for (int ks = 0; ks < 4; ks++) {
                const uint32_t kb = ks * 32 + koff;
                uint32_t ah[2][4], a2[2][4];
#pragma unroll
                for (int i = 0; i < 2; i++) {
                    ldm_x4(ah[i], AH + roffA[i] + (kb ^ rxA[i]));
                    ldm_x4(a2[i], AL + roffA[i] + (kb ^ rxA[i]));
                }
#pragma unroll
                for (int j = 0; j < 4; j++) {
                    uint32_t bh[4], b2[4];
                    ldm_x4(bh, WHs + roffB[j] + (kb ^ rxB[j]));
                    ldm_x4(b2, WLs + roffB[j] + (kb ^ rxB[j]));
#pragma unroll
                    for (int i = 0; i < 2; i++) {
                        mma16816(acc1[i][j*2+0], ah[i], bh[0], bh[2]);
                        mma16816(acc1[i][j*2+1], ah[i], bh[1], bh[3]);
                        mma16816(acc2[i][j*2+0], a2[i], b2[0], b2[2]);
                        mma16816(acc2[i][j*2+1], a2[i], b2[1], b2[3]);
                    }
                }
            }
        }

        // epilogue (overlaps the two in-flight loads of the next tile)
        const int rbase = row0 + wm * 32 + (lane >> 2);
        const int cbase = wn * 64 + (lane & 3) * 2;
#pragma unroll
        for (int i = 0; i < 2; i++) {
#pragma unroll
            for (int g = 0; g < 8; g++) {
                const int c  = cbase + g * 8;
                const int cg = col0 + c;
                const int r0 = rbase + i * 16;
                float b0 = bias ? bias[cg]     : 0.f;
                float b1 = bias ? bias[cg + 1] : 0.f;
                float v00 = combine(acc1[i][g][0], acc2[i][g][0]) + b0;
                float v01 = combine(acc1[i][g][1], acc2[i][g][1]) + b1;
                float v10 = combine(acc1[i][g][2], acc2[i][g][2]) + b0;
                float v11 = combine(acc1[i][g][3], acc2[i][g][3]) + b1;
                if (mode == 0) {
                    *(float2*)(Cf + (size_t)r0 * ldc + cg)     = make_float2(v00, v01);
                    *(float2*)(Cf + (size_t)(r0+8) * ldc + cg) = make_float2(v10, v11);
                } else {
                    if (mode == 1) {
                        v00 = gelu_exact(v00); v01 = gelu_exact(v01);
                        v10 = gelu_exact(v10); v11 = gelu_exact(v11);
                    }
                    __half h00, l00, h01, l01, h10, l10, h11, l11;
                    split_act(v00, h00, l00); split_act(v01, h01, l01);
                    split_act(v10, h10, l10); split_act(v11, h11, l11);
                    *(__half2*)(Chi + (size_t)r0 * ldc + cg)     = __halves2half2(h00, h01);
                    *(__half2*)(Chi + (size_t)(r0+8) * ldc + cg) = __halves2half2(h10, h11);
                    *(__half2*)(Clo + (size_t)r0 * ldc + cg)     = __halves2half2(l00, l01);
                    *(__half2*)(Clo + (size_t)(r0+8) * ldc + cg) = __halves2half2(l10, l11);
                }
            }
        }
    }
}

// ---------------- flash attention: QTILE=64, 2 CTAs/SM (R11 proven) ----------
#define QTILE 64
#define KTILE 64
#define QP 68
#define KP 68
#define VP 68
#define SP 68
#define AQ_OFF 0
#define AK_OFF (AQ_OFF + 64*QP)
#define AV_OFF (AK_OFF + 64*KP)
#define AS_OFF (AV_OFF + 64*VP)
#define ATTN_SMEM ((AS_OFF + 64*SP) * 4)

__global__ __launch_bounds__(256)
void attn_flash(const float* __restrict__ qkv,
                __half* __restrict__ ahi, __half* __restrict__ alo) {
    extern __shared__ float sm[];
    float* Qs = sm + AQ_OFF;
    float* Kt = sm + AK_OFF;
    float* Vs = sm + AV_OFF;
    float* Ss = sm + AS_OFF;

    const int tid = threadIdx.x;
    const int tx = tid & 15, ty = tid >> 4;
    const int bh = blockIdx.y;
    const int b  = bh >> 4;
    const int h  = bh & 15;
    const int qt = (int)gridDim.x - 1 - (int)blockIdx.x;
    const int q0 = qt * QTILE;

#pragma unroll
    for (int i = 0; i < 4; i++) {
        int idx = tid + i * 256;
        int r = idx >> 4, c = idx & 15;
        float4 v = *(const float4*)(qkv + ((size_t)((q0 + r) * BATCH + b)) * D3 + h * DKH + c * 4);
        v.x *= ATT_SCALE; v.y *= ATT_SCALE; v.z *= ATT_SCALE; v.w *= ATT_SCALE;
        *(float4*)(Qs + r * QP + c * 4) = v;
    }

    float acc[4][4];
    float mrow[4], lrow[4];
#pragma unroll
    for (int i = 0; i < 4; i++) {
        mrow[i] = -1e30f; lrow[i] = 0.f;
#pragma unroll
        for (int j = 0; j < 4; j++) acc[i][j] = 0.f;
    }

    __syncthreads();

    const int ntiles = qt + 1;

    for (int kt = 0; kt < ntiles; kt++) {
        const int s0 = kt * KTILE;
#pragma unroll
        for (int i = 0; i < 4; i++) {
            int idx = tid + i * 256;
            int r = idx >> 4, c = idx & 15;
            const float* base = qkv + ((size_t)((s0 + r) * BATCH + b)) * D3 + h * DKH + c * 4;
            float4 kv = *(const float4*)(base + D);
            float4 vv = *(const float4*)(base + 2 * D);
            Kt[(c*4+0) * KP + r] = kv.x;
            Kt[(c*4+1) * KP + r] = kv.y;
            Kt[(c*4+2) * KP + r] = kv.z;
            Kt[(c*4+3) * KP + r] = kv.w;
            *(float4*)(Vs + r * VP + c * 4) = vv;
        }
        __syncthreads();

        float sreg[4][4];
#pragma unroll
        for (int i = 0; i < 4; i++)
#pragma unroll
            for (int j = 0; j < 4; j++) sreg[i][j] = 0.f;
#pragma unroll 8
        for (int d = 0; d < 64; d++) {
            const float4 kq = *(const float4*)(Kt + d * KP + tx * 4);
#pragma unroll
            for (int i = 0; i < 4; i++) {
                float qv = Qs[(ty * 4 + i) * QP + d];
                sreg[i][0] += qv * kq.x;
                sreg[i][1] += qv * kq.y;
                sreg[i][2] += qv * kq.z;
                sreg[i][3] += qv * kq.w;
            }
        }
#pragma unroll
        for (int i = 0; i < 4; i++) {
            const int qg = q0 + ty * 4 + i;
            if (s0 + tx*4 + 0 > qg) sreg[i][0] = -1e30f;
            if (s0 + tx*4 + 1 > qg) sreg[i][1] = -1e30f;
            if (s0 + tx*4 + 2 > qg) sreg[i][2] = -1e30f;
            if (s0 + tx*4 + 3 > qg) sreg[i][3] = -1e30f;
        }

        float frow[4];
#pragma unroll
        for (int i = 0; i < 4; i++) {
            float tmax = fmaxf(fmaxf(sreg[i][0], sreg[i][1]),
                               fmaxf(sreg[i][2], sreg[i][3]));
#pragma unroll
            for (int o = 8; o > 0; o >>= 1)
                tmax = fmaxf(tmax, __shfl_xor_sync(0xffffffffu, tmax, o));
            const float mn = fmaxf(mrow[i], tmax);
            frow[i] = __expf(mrow[i] - mn);
            mrow[i] = mn;
            float p0 = __expf(sreg[i][0] - mn);
            float p1 = __expf(sreg[i][1] - mn);
            float p2 = __expf(sreg[i][2] - mn);
            float p3 = __expf(sreg[i][3] - mn);
            float rs = p0 + p1 + p2 + p3;
#pragma unroll
            for (int o = 8; o > 0; o >>= 1)
                rs += __shfl_xor_sync(0xffffffffu, rs, o);
            lrow[i] = lrow[i] * frow[i] + rs;
            *(float4*)(Ss + (ty * 4 + i) * SP + tx * 4) = make_float4(p0, p1, p2, p3);
            acc[i][0] *= frow[i]; acc[i][1] *= frow[i];
            acc[i][2] *= frow[i]; acc[i][3] *= frow[i];
        }
        __syncthreads();

#pragma unroll 4
        for (int s = 0; s < 64; s++) {
            const float4 v4 = *(const float4*)(Vs + s * VP + tx * 4);
#pragma unroll
            for (int i = 0; i < 4; i++) {
                const float p = Ss[(ty * 4 + i) * SP + s];
                acc[i][0] += p * v4.x;
                acc[i][1] += p * v4.y;
                acc[i][2] += p * v4.z;
                acc[i][3] += p * v4.w;
            }
        }
        __syncthreads();
    }

#pragma unroll
    for (int i = 0; i < 4; i++) {
        const int q = ty * 4 + i;
        const float inv = 1.f / lrow[i];
        float v0 = acc[i][0] * inv, v1 = acc[i][1] * inv;
        float v2 = acc[i][2] * inv, v3 = acc[i][3] * inv;
        __half h0, l0, h1, l1, h2, l2, h3, l3;
        split_act(v0, h0, l0); split_act(v1, h1, l1);
        split_act(v2, h2, l2); split_act(v3, h3, l3);
        size_t base = ((size_t)((q0 + q) * BATCH + b)) * D + h * DKH + tx * 4;
        *(__half2*)(ahi + base)     = __halves2half2(h0, h1);
        *(__half2*)(ahi + base + 2) = __halves2half2(h2, h3);
        *(__half2*)(alo + base)     = __halves2half2(l0, l1);
        *(__half2*)(alo + base + 2) = __halves2half2(l2, l3);
    }
}

// ---------------- fused GRU + LN + splits (one block per token) --------------
__global__ __launch_bounds__(256)
void gru_ln_split(float* __restrict__ px, const float* __restrict__ gate,
                  const float* __restrict__ bg,
                  const float* __restrict__ g, const float* __restrict__ b,
                  __half* __restrict__ cathi, __half* __restrict__ catlo,
                  __half* __restrict__ lnhi, __half* __restrict__ lnlo,
                  float* __restrict__ outf) {
    const int n = blockIdx.x;
    const int tid = threadIdx.x;
    const float* grow = gate + (size_t)n * D3;
    float vals[4];
    float s = 0.f, sq = 0.f;
#pragma unroll
    for (int k = 0; k < 4; k++) {
        const int j = tid + k * 256;
        float gr = grow[j];
        float gz = grow[D + j];
        float gh = grow[2 * D + j];
        float r = 1.f / (1.f + __expf(-gr));
        float z = 1.f / (1.f + __expf(-(gz - bg[j])));
        float hh = tanhf(gh * r);
        float xv = px[(size_t)n * D + j];
        float v = (1.f - z) * xv + z * hh;
        px[(size_t)n * D + j] = v;
        vals[k] = v;
        __half h, l; split_act(v, h, l);
        cathi[(size_t)n * D2 + j] = h;
        catlo[(size_t)n * D2 + j] = l;
        s += v; sq += v * v;
    }
    __shared__ float rs[256], rq[256];
    rs[tid] = s; rq[tid] = sq; __syncthreads();
    for (int off = 128; off > 0; off >>= 1) {
        if (tid < off) { rs[tid] += rs[tid + off]; rq[tid] += rq[tid + off]; }
        __syncthreads();
    }
    const float mu  = rs[0] * (1.f / D);
    const float var = rq[0] * (1.f / D) - mu * mu;
    const float inv = rsqrtf(var + 1e-6f);
#pragma unroll
    for (int k = 0; k < 4; k++) {
        const int j = tid + k * 256;
        float y = (vals[k] - mu) * inv * g[j] + b[j];
        if (outf) {
            outf[(size_t)n * D + j] = y;
        } else {
            __half h, l; split_act(y, h, l);
            lnhi[(size_t)n * D + j] = h;
            lnlo[(size_t)n * D + j] = l;
        }
    }
}

// ---------------- fused GELU+PE + LN + splits (layer-0 entry) ----------------
__global__ __launch_bounds__(256)
void gelu_pe_ln_split(float* __restrict__ px, const float* __restrict__ pe,
                      const float* __restrict__ g, const float* __restrict__ b,
                      __half* __restrict__ cathi, __half* __restrict__ catlo,
                      __half* __restrict__ lnhi, __half* __restrict__ lnlo) {
    const int n = blockIdx.x;
    const int t = n >> 1;
    const int tid = threadIdx.x;
    float vals[4];
    float s = 0.f, sq = 0.f;
#pragma unroll
    for (int k = 0; k < 4; k++) {
        const int j = tid + k * 256;
        float v = gelu_exact(px[(size_t)n * D + j]) + pe[(size_t)t * D + j];
        px[(size_t)n * D + j] = v;
        vals[k] = v;
        __half h, l; split_act(v, h, l);
        cathi[(size_t)n * D2 + j] = h;
        catlo[(size_t)n * D2 + j] = l;
        s += v; sq += v * v;
    }
    __shared__ float rs[256], rq[256];
    rs[tid] = s; rq[tid] = sq; __syncthreads();
    for (int off = 128; off > 0; off >>= 1) {
        if (tid < off) { rs[tid] += rs[tid + off]; rq[tid] += rq[tid + off]; }
        __syncthreads();
    }
    const float mu  = rs[0] * (1.f / D);
    const float var = rq[0] * (1.f / D) - mu * mu;
    const float inv = rsqrtf(var + 1e-6f);
#pragma unroll
    for (int k = 0; k < 4; k++) {
        const int j = tid + k * 256;
        float y = (vals[k] - mu) * inv * g[j] + b[j];
        __half h, l; split_act(y, h, l);
        lnhi[(size_t)n * D + j] = h;
        lnlo[(size_t)n * D + j] = l;
    }
}

// ---------------- f32 -> fp16 pair splits ----------------
__global__ void cvt_split_act(const float4* __restrict__ x,
                              __half2* __restrict__ hi, __half2* __restrict__ lo,
                              int n4) {
    int i = blockIdx.x * blockDim.x + threadIdx.x;
    if (i >= n4) return;
    float4 v = x[i];
    __half h0, l0, h1, l1, h2, l2, h3, l3;
    split_act(v.x, h0, l0); split_act(v.y, h1, l1);
    split_act(v.z, h2, l2); split_act(v.w, h3, l3);
    hi[2*i]   = __halves2half2(h0, h1);
    hi[2*i+1] = __halves2half2(h2, h3);
    lo[2*i]   = __halves2half2(l0, l1);
    lo[2*i+1] = __halves2half2(l2, l3);
}

__global__ void cvt_split_wgt(const float4* __restrict__ x,
                              __half2* __restrict__ hi, __half2* __restrict__ w2,
                              int n4) {
    int i = blockIdx.x * blockDim.x + threadIdx.x;
    if (i >= n4) return;
    float4 v = x[i];
    __half h0, l0, h1, l1, h2, l2, h3, l3;
    split_wgt(v.x, h0, l0); split_wgt(v.y, h1, l1);
    split_wgt(v.z, h2, l2); split_wgt(v.w, h3, l3);
    hi[2*i]   = __halves2half2(h0, h1);
    hi[2*i+1] = __halves2half2(h2, h3);
    w2[2*i]   = __halves2half2(l0, l1);
    w2[2*i+1] = __halves2half2(l2, l3);
}

// ---------------- driver ----------------
extern "C" void kernel_launch(void* const* d_in, const int* in_sizes, int n_in,
                              void* d_out, int out_size) {
    const float* x_in  = (const float*)d_in[0];
    const float* pe    = (const float*)d_in[1];
    const float* in_w  = (const float*)d_in[2];
    const float* in_b  = (const float*)d_in[3];
    const float* qkv_w = (const float*)d_in[4];
    const float* out_w = (const float*)d_in[5];
    const float* out_b = (const float*)d_in[6];
    const float* ln1_g = (const float*)d_in[7];
    const float* ln1_b = (const float*)d_in[8];
    const float* ln2_g = (const float*)d_in[9];
    const float* ln2_b = (const float*)d_in[10];
    const float* ff_w1 = (const float*)d_in[11];
    const float* ff_b1 = (const float*)d_in[12];
    const float* ff_w2 = (const float*)d_in[13];
    const float* ff_b2 = (const float*)d_in[14];
    const float* g1_w  = (const float*)d_in[15];
    const float* g1_bg = (const float*)d_in[16];
    const float* g2_w  = (const float*)d_in[17];
    const float* g2_bg = (const float*)d_in[18];
    const float* on_g  = (const float*)d_in[19];
    const float* on_b  = (const float*)d_in[20];

    float *px, *pqkv, *pgate;
    __half *chi, *clo, *lhi, *llo, *phi, *plo, *fhi, *flo, *xhi, *xlo;
    __half *w_in_h, *w_in_l, *w_qkv_h, *w_qkv_l, *w_out_h, *w_out_l;
    __half *w_f1_h, *w_f1_l, *w_f2_h, *w_f2_l, *w_g1_h, *w_g1_l, *w_g2_h, *w_g2_l;
    cudaGetSymbolAddress((void**)&px,    g_x);
    cudaGetSymbolAddress((void**)&pqkv,  g_qkv);
    cudaGetSymbolAddress((void**)&pgate, g_gate);
    cudaGetSymbolAddress((void**)&chi,   g_chi);  cudaGetSymbolAddress((void**)&clo,   g_clo);
    cudaGetSymbolAddress((void**)&lhi,   g_lhi);  cudaGetSymbolAddress((void**)&llo,   g_llo);
    cudaGetSymbolAddress((void**)&phi,   g_phi);  cudaGetSymbolAddress((void**)&plo,   g_plo);
    cudaGetSymbolAddress((void**)&fhi,   g_fhi);  cudaGetSymbolAddress((void**)&flo,   g_flo);
    cudaGetSymbolAddress((void**)&xhi,   g_xhi);  cudaGetSymbolAddress((void**)&xlo,   g_xlo);
    cudaGetSymbolAddress((void**)&w_in_h,  wb_in_hi);  cudaGetSymbolAddress((void**)&w_in_l,  wb_in_lo);
    cudaGetSymbolAddress((void**)&w_qkv_h, wb_qkv_hi); cudaGetSymbolAddress((void**)&w_qkv_l, wb_qkv_lo);
    cudaGetSymbolAddress((void**)&w_out_h, wb_out_hi); cudaGetSymbolAddress((void**)&w_out_l, wb_out_lo);
    cudaGetSymbolAddress((void**)&w_f1_h,  wb_f1_hi);  cudaGetSymbolAddress((void**)&w_f1_l,  wb_f1_lo);
    cudaGetSymbolAddress((void**)&w_f2_h,  wb_f2_hi);  cudaGetSymbolAddress((void**)&w_f2_l,  wb_f2_lo);
    cudaGetSymbolAddress((void**)&w_g1_h,  wb_g1_hi);  cudaGetSymbolAddress((void**)&w_g1_l,  wb_g1_lo);
    cudaGetSymbolAddress((void**)&w_g2_h,  wb_g2_hi);  cudaGetSymbolAddress((void**)&w_g2_l,  wb_g2_lo);

    cudaFuncSetAttribute(gemm_mma, cudaFuncAttributeMaxDynamicSharedMemorySize, SMEM_BYTES);
    cudaFuncSetAttribute(attn_flash, cudaFuncAttributeMaxDynamicSharedMemorySize, ATTN_SMEM);

    int nsm = 148;
    cudaDeviceGetAttribute(&nsm, cudaDevAttrMultiProcessorCount, 0);

    const int EW = 256;
    auto cvtgrid = [](int n) { return (n / 4 + 255) / 256; };

    cvt_split_wgt<<<cvtgrid(D*D),        EW>>>((const float4*)in_w,  (__half2*)w_in_h,  (__half2*)w_in_l,  D*D/4);
    cvt_split_wgt<<<cvtgrid(LNUM*D3*D),  EW>>>((const float4*)qkv_w, (__half2*)w_qkv_h, (__half2*)w_qkv_l, LNUM*D3*D/4);
    cvt_split_wgt<<<cvtgrid(LNUM*D*D),   EW>>>((const float4*)out_w, (__half2*)w_out_h, (__half2*)w_out_l, LNUM*D*D/4);
    cvt_split_wgt<<<cvtgrid(LNUM*FFD*D), EW>>>((const float4*)ff_w1, (__half2*)w_f1_h,  (__half2*)w_f1_l,  LNUM*FFD*D/4);
    cvt_split_wgt<<<cvtgrid(LNUM*D*FFD), EW>>>((const float4*)ff_w2, (__half2*)w_f2_h,  (__half2*)w_f2_l,  LNUM*D*FFD/4);
    cvt_split_wgt<<<cvtgrid(LNUM*D3*D2), EW>>>((const float4*)g1_w,  (__half2*)w_g1_h,  (__half2*)w_g1_l,  LNUM*D3*D2/4);
    cvt_split_wgt<<<cvtgrid(LNUM*D3*D2), EW>>>((const float4*)g2_w,  (__half2*)w_g2_h,  (__half2*)w_g2_l,  LNUM*D3*D2/4);
    cvt_split_act<<<cvtgrid(NTOK*D),     EW>>>((const float4*)x_in,  (__half2*)xhi,     (__half2*)xlo,     NTOK*D/4);

    const int gxD  = D   / 128, ntD  = gxD  * (NTOK / 128);
    const int gxD3 = D3  / 128, ntD3 = gxD3 * (NTOK / 128);
    const int gxFF = FFD / 128, ntFF = gxFF * (NTOK / 128);
    const int cD   = ntD  < nsm ? ntD  : nsm;
    const int cD3  = ntD3 < nsm ? ntD3 : nsm;
    const int cFF  = ntFF < nsm ? ntFF : nsm;

    gemm_mma<<<cD, 256, SMEM_BYTES>>>(xhi, xlo, D, w_in_h, w_in_l, in_b, px, 0, 0, D, D, 0, gxD, ntD);
    gelu_pe_ln_split<<<NTOK, 256>>>(px, pe, ln1_g, ln1_b, chi, clo, lhi, llo);

    for (int l = 0; l < LNUM; l++) {
        const __half* qwh = w_qkv_h + (size_t)l*D3*D;  const __half* qwl = w_qkv_l + (size_t)l*D3*D;
        const __half* owh = w_out_h + (size_t)l*D*D;   const __half* owl = w_out_l + (size_t)l*D*D;
        const __half* f1h = w_f1_h  + (size_t)l*FFD*D; const __half* f1l = w_f1_l  + (size_t)l*FFD*D;
        const __half* f2h = w_f2_h  + (size_t)l*D*FFD; const __half* f2l = w_f2_l  + (size_t)l*D*FFD;
        const __half* g1h = w_g1_h  + (size_t)l*D3*D2; const __half* g1l = w_g1_l  + (size_t)l*D3*D2;
        const __half* g2h = w_g2_h  + (size_t)l*D3*D2; const __half* g2l = w_g2_l  + (size_t)l*D3*D2;
        const float* ob  = out_b + (size_t)l*D;
        const float* l2g = ln2_g + (size_t)l*D;  const float* l2b = ln2_b + (size_t)l*D;
        const float* fb1 = ff_b1 + (size_t)l*FFD;
        const float* fb2 = ff_b2 + (size_t)l*D;
        const float* gb1 = g1_bg + (size_t)l*D;
        const float* gb2 = g2_bg + (size_t)l*D;
        const float* ng = (l + 1 < LNUM) ? ln1_g + (size_t)(l+1)*D : on_g;
        const float* nb = (l + 1 < LNUM) ? ln1_b + (size_t)(l+1)*D : on_b;
        float* fout = (l + 1 < LNUM) ? nullptr : (float*)d_out;

        // attention block
        gemm_mma<<<cD3, 256, SMEM_BYTES>>>(lhi, llo, D, qwh, qwl, nullptr, pqkv, 0, 0, D3, D, 0, gxD3, ntD3);
        attn_flash<<<dim3(TT/QTILE, BATCH*H), 256, ATTN_SMEM>>>(pqkv, phi, plo);
        gemm_mma<<<cD, 256, SMEM_BYTES>>>(phi, plo, D, owh, owl, ob, 0, chi + D, clo + D, D2, D, 2, gxD, ntD);
        gemm_mma<<<cD3, 256, SMEM_BYTES>>>(chi, clo, D2, g1h, g1l, nullptr, pgate, 0, 0, D3, D2, 0, gxD3, ntD3);
        gru_ln_split<<<NTOK, 256>>>(px, pgate, gb1, l2g, l2b, chi, clo, lhi, llo, nullptr);

        // feed-forward block
        gemm_mma<<<cFF, 256, SMEM_BYTES>>>(lhi, llo, D, f1h, f1l, fb1, 0, fhi, flo, FFD, D, 1, gxFF, ntFF);
        gemm_mma<<<cD, 256, SMEM_BYTES>>>(fhi, flo, FFD, f2h, f2l, fb2, 0, chi + D, clo + D, D2, FFD, 2, gxD, ntD);
        gemm_mma<<<cD3, 256, SMEM_BYTES>>>(chi, clo, D2, g2h, g2l, nullptr, pgate, 0, 0, D3, D2, 0, gxD3, ntD3);
        gru_ln_split<<<NTOK, 256>>>(px, pgate, gb2, ng, nb, chi, clo, lhi, llo, fout);
    }
}

// round 13
// speedup vs baseline: 1.0922x; 1.0922x over previous
#include <cuda_runtime.h>
#include <cuda_fp16.h>
#include <math.h>
#include <stdint.h>

// ---------------- problem constants ----------------
#define LNUM  6
#define D     1024
#define H     16
#define DKH   64
#define FFD   4096
#define TT    1024
#define BATCH 2
#define NTOK  2048
#define D3    3072
#define D2    2048
#define ATT_SCALE 0.125f
#define SCL   0.015625f        // 2^-6
#define SCLI  64.0f            // 2^6

#define SWZ(o) ((o) ^ (((o) >> 3) & 0x70))

// ---------------- scratch (device globals; no allocs allowed) ----------------
__device__ float g_x   [NTOK*D];     // residual stream (f32)
__device__ float g_qkv [NTOK*D3];
__device__ float g_gate[NTOK*D3];
__device__ __half g_chi[NTOK*D2],  g_clo[NTOK*D2];   // concat [x,y] hi / A2
__device__ __half g_lhi[NTOK*D],   g_llo[NTOK*D];    // LN output hi / A2
__device__ __half g_phi[NTOK*D],   g_plo[NTOK*D];    // attn output hi / A2
__device__ __half g_fhi[NTOK*FFD], g_flo[NTOK*FFD];  // FF hidden hi / A2
__device__ __half g_xhi[NTOK*D],   g_xlo[NTOK*D];    // input x split
__device__ __half wb_in_hi [D*D],        wb_in_lo [D*D];
__device__ __half wb_qkv_hi[LNUM*D3*D],  wb_qkv_lo[LNUM*D3*D];
__device__ __half wb_out_hi[LNUM*D*D],   wb_out_lo[LNUM*D*D];
__device__ __half wb_f1_hi [LNUM*FFD*D], wb_f1_lo [LNUM*FFD*D];
__device__ __half wb_f2_hi [LNUM*D*FFD], wb_f2_lo [LNUM*D*FFD];
__device__ __half wb_g1_hi [LNUM*D3*D2], wb_g1_lo [LNUM*D3*D2];
__device__ __half wb_g2_hi [LNUM*D3*D2], wb_g2_lo [LNUM*D3*D2];

// ---------------- PTX helpers (portable: sm_80-level) ----------------
__device__ __forceinline__ uint32_t smem_u32(const void* p) {
    uint32_t a;
    asm("{ .reg .u64 t; cvta.to.shared.u64 t, %1; cvt.u32.u64 %0, t; }" : "=r"(a) : "l"(p));
    return a;
}
__device__ __forceinline__ void cp16(uint32_t d, const void* g) {
    asm volatile("cp.async.cg.shared.global [%0], [%1], 16;" :: "r"(d), "l"(g));
}
__device__ __forceinline__ void ldm_x4(uint32_t* f, uint32_t addr) {
    asm volatile("ldmatrix.sync.aligned.m8n8.x4.shared.b16 {%0,%1,%2,%3}, [%4];"
                 : "=r"(f[0]), "=r"(f[1]), "=r"(f[2]), "=r"(f[3]) : "r"(addr));
}
__device__ __forceinline__ void mma16816(float* c, const uint32_t* a, uint32_t b0, uint32_t b1) {
    asm volatile(
        "mma.sync.aligned.m16n8k16.row.col.f32.f16.f16.f32 "
        "{%0,%1,%2,%3}, {%4,%5,%6,%7}, {%8,%9}, {%0,%1,%2,%3};"
        : "+f"(c[0]), "+f"(c[1]), "+f"(c[2]), "+f"(c[3])
        : "r"(a[0]), "r"(a[1]), "r"(a[2]), "r"(a[3]), "r"(b0), "r"(b1));
}
__device__ __forceinline__ float gelu_exact(float v) { return v * normcdff(v); }

// Activation split: hi = fp16(v); A2 = fp16((v - hi) + hi*2^-6)
__device__ __forceinline__ void split_act(float v, __half& h, __half& a2) {
    h = __float2half_rn(v);
    float lo = v - __half2float(h);
    a2 = __float2half_rn(fmaf(__half2float(h), SCL, lo));
}
// Weight split: hi = fp16(w); W2 = fp16(hi + (w - hi)*2^6)
__device__ __forceinline__ void split_wgt(float w, __half& h, __half& w2) {
    h = __float2half_rn(w);
    float lo = w - __half2float(h);
    w2 = __float2half_rn(fmaf(lo, SCLI, __half2float(h)));
}
// Final combine: C = acc1*(1 - 2^-6) + acc2
__device__ __forceinline__ float combine(float a1, float a2) {
    return fmaf(a1, 1.0f - SCL, a2);
}

// ---------------- fp16 2-MMA GEMM (persistent, 2-stage — R11 proven) ---------
#define STAGE_B 65536
#define SMEM_BYTES (2*STAGE_B)

__global__ __launch_bounds__(256)
void gemm_mma(const __half* __restrict__ Ahi, const __half* __restrict__ A2p,
              int lda,
              const __half* __restrict__ Whi, const __half* __restrict__ W2p,
              const float* __restrict__ bias,
              float* __restrict__ Cf,
              __half* __restrict__ Chi, __half* __restrict__ Clo,
              int ldc, int K, int mode, int gx, int ntiles)
{
    extern __shared__ char smem[];
    const uint32_t sb = smem_u32(smem);
    const int tid  = threadIdx.x;
    const int wid  = tid >> 5;
    const int lane = tid & 31;
    const int wm   = wid >> 1;
    const int wn   = wid & 1;

    const int lr   = lane & 15;
    const int koff = (lane >> 4) << 4;
    uint32_t roffA[2], rxA[2], roffB[4], rxB[4];
#pragma unroll
    for (int i = 0; i < 2; i++) {
        int r = wm * 32 + i * 16 + lr;
        roffA[i] = r * 128; rxA[i] = (r & 7) << 4;
    }
#pragma unroll
    for (int j = 0; j < 4; j++) {
        int r = wn * 64 + j * 16 + lr;
        roffB[j] = r * 128; rxB[j] = (r & 7) << 4;
    }

    const int nch = K / 64;
    const int ldr = tid >> 3, ldc4 = tid & 7;

    auto issue = [&](int tt, int cc, int stage) {
        const int r0 = (tt / gx) * 128;
        const int c0 = (tt % gx) * 128;
        const int kbase = cc * 64;
        const uint32_t st = sb + stage * STAGE_B;
#pragma unroll
        for (int i = 0; i < 4; i++) {
            int r = ldr + i * 32;
            uint32_t off = SWZ((uint32_t)(r * 128 + ldc4 * 16));
            size_t sa = (size_t)(r0 + r) * lda + kbase + ldc4 * 8;
            size_t sw = (size_t)(c0 + r) * K   + kbase + ldc4 * 8;
            cp16(st +         off, Ahi + sa);
            cp16(st + 16384 + off, A2p + sa);
            cp16(st + 32768 + off, Whi + sw);
            cp16(st + 49152 + off, W2p + sw);
        }
        asm volatile("cp.async.commit_group;");
    };

    const int grid = (int)gridDim.x;
    int cur_stage = 0;
    issue(blockIdx.x, 0, 0);

    for (int t = blockIdx.x; t < ntiles; t += grid) {
        const int row0 = (t / gx) * 128;
        const int col0 = (t % gx) * 128;

        float acc1[2][8][4], acc2[2][8][4];
#pragma unroll
        for (int i = 0; i < 2; i++)
#pragma unroll
            for (int g = 0; g < 8; g++)
#pragma unroll
                for (int q = 0; q < 4; q++) { acc1[i][g][q] = 0.f; acc2[i][g][q] = 0.f; }

        for (int cc = 0; cc < nch; cc++) {
            asm volatile("cp.async.wait_group 0;");
            __syncthreads();
            const int nxt = cur_stage ^ 1;
            if (cc + 1 < nch)              issue(t, cc + 1, nxt);
            else if (t + grid < ntiles)    issue(t + grid, 0, nxt);

            const uint32_t AH = sb + cur_stage * STAGE_B;
            const uint32_t AL = AH + 16384;
            const uint32_t WHs = AH + 32768;
            const uint32_t WLs = AH + 49152;
#pragma unroll
            for (int ks = 0; ks < 4; ks++) {
                const uint32_t kb = ks * 32 + koff;
                uint32_t ah[2][4], a2[2][4];
#pragma unroll
                for (int i = 0; i < 2; i++) {
                    ldm_x4(ah[i], AH + roffA[i] + (kb ^ rxA[i]));
                    ldm_x4(a2[i], AL + roffA[i] + (kb ^ rxA[i]));
                }
#pragma unroll
                for (int j = 0; j < 4; j++) {
                    uint32_t bh[4], b2[4];
                    ldm_x4(bh, WHs + roffB[j] + (kb ^ rxB[j]));
                    ldm_x4(b2, WLs + roffB[j] + (kb ^ rxB[j]));
#pragma unroll
                    for (int i = 0; i < 2; i++) {
                        mma16816(acc1[i][j*2+0], ah[i], bh[0], bh[2]);
                        mma16816(acc1[i][j*2+1], ah[i], bh[1], bh[3]);
                        mma16816(acc2[i][j*2+0], a2[i], b2[0], b2[2]);
                        mma16816(acc2[i][j*2+1], a2[i], b2[1], b2[3]);
                    }
                }
            }
            cur_stage ^= 1;
        }

        const int rbase = row0 + wm * 32 + (lane >> 2);
        const int cbase = wn * 64 + (lane & 3) * 2;
#pragma unroll
        for (int i = 0; i < 2; i++) {
#pragma unroll
            for (int g = 0; g < 8; g++) {
                const int c  = cbase + g * 8;
                const int cg = col0 + c;
                const int r0 = rbase + i * 16;
                float b0 = bias ? bias[cg]     : 0.f;
                float b1 = bias ? bias[cg + 1] : 0.f;
                float v00 = combine(acc1[i][g][0], acc2[i][g][0]) + b0;
                float v01 = combine(acc1[i][g][1], acc2[i][g][1]) + b1;
                float v10 = combine(acc1[i][g][2], acc2[i][g][2]) + b0;
                float v11 = combine(acc1[i][g][3], acc2[i][g][3]) + b1;
                if (mode == 0) {
                    *(float2*)(Cf + (size_t)r0 * ldc + cg)     = make_float2(v00, v01);
                    *(float2*)(Cf + (size_t)(r0+8) * ldc + cg) = make_float2(v10, v11);
                } else {
                    if (mode == 1) {
                        v00 = gelu_exact(v00); v01 = gelu_exact(v01);
                        v10 = gelu_exact(v10); v11 = gelu_exact(v11);
                    }
                    __half h00, l00, h01, l01, h10, l10, h11, l11;
                    split_act(v00, h00, l00); split_act(v01, h01, l01);
                    split_act(v10, h10, l10); split_act(v11, h11, l11);
                    *(__half2*)(Chi + (size_t)r0 * ldc + cg)     = __halves2half2(h00, h01);
                    *(__half2*)(Chi + (size_t)(r0+8) * ldc + cg) = __halves2half2(h10, h11);
                    *(__half2*)(Clo + (size_t)r0 * ldc + cg)     = __halves2half2(l00, l01);
                    *(__half2*)(Clo + (size_t)(r0+8) * ldc + cg) = __halves2half2(l10, l11);
                }
            }
        }
    }
}

// ---------------- flash attention: QTILE=64, 2 CTAs/SM + K/V reg prefetch ----
#define QTILE 64
#define KTILE 64
#define QP 68
#define KP 68
#define VP 68
#define SP 68
#define AQ_OFF 0
#define AK_OFF (AQ_OFF + 64*QP)
#define AV_OFF (AK_OFF + 64*KP)
#define AS_OFF (AV_OFF + 64*VP)
#define ATTN_SMEM ((AS_OFF + 64*SP) * 4)

__global__ __launch_bounds__(256)
void attn_flash(const float* __restrict__ qkv,
                __half* __restrict__ ahi, __half* __restrict__ alo) {
    extern __shared__ float sm[];
    float* Qs = sm + AQ_OFF;
    float* Kt = sm + AK_OFF;
    float* Vs = sm + AV_OFF;
    float* Ss = sm + AS_OFF;

    const int tid = threadIdx.x;
    const int tx = tid & 15, ty = tid >> 4;
    const int bh = blockIdx.y;
    const int b  = bh >> 4;
    const int h  = bh & 15;
    const int qt = (int)gridDim.x - 1 - (int)blockIdx.x;   // heavy tiles first
    const int q0 = qt * QTILE;

#pragma unroll
    for (int i = 0; i < 4; i++) {
        int idx = tid + i * 256;
        int r = idx >> 4, c = idx & 15;
        float4 v = *(const float4*)(qkv + ((size_t)((q0 + r) * BATCH + b)) * D3 + h * DKH + c * 4);
        v.x *= ATT_SCALE; v.y *= ATT_SCALE; v.z *= ATT_SCALE; v.w *= ATT_SCALE;
        *(float4*)(Qs + r * QP + c * 4) = v;
    }

    float acc[4][4];
    float mrow[4], lrow[4];
#pragma unroll
    for (int i = 0; i < 4; i++) {
        mrow[i] = -1e30f; lrow[i] = 0.f;
#pragma unroll
        for (int j = 0; j < 4; j++) acc[i][j] = 0.f;
    }

    const int ntiles = qt + 1;

    // K/V register prefetch buffers (tile kt+1 loaded during compute of kt)
    float4 pk[4], pv[4];
    auto prefetch = [&](int kt) {
        const int s0 = kt * KTILE;
#pragma unroll
        for (int i = 0; i < 4; i++) {
            int idx = tid + i * 256;
            int r = idx >> 4, c = idx & 15;
            const float* base = qkv + ((size_t)((s0 + r) * BATCH + b)) * D3 + h * DKH + c * 4;
            pk[i] = *(const float4*)(base + D);
            pv[i] = *(const float4*)(base + 2 * D);
        }
    };

    prefetch(0);
    __syncthreads();

    for (int kt = 0; kt < ntiles; kt++) {
        const int s0 = kt * KTILE;
        // store prefetched tile into smem (K transposed)
#pragma unroll
        for (int i = 0; i < 4; i++) {
            int idx = tid + i * 256;
            int r = idx >> 4, c = idx & 15;
            Kt[(c*4+0) * KP + r] = pk[i].x;
            Kt[(c*4+1) * KP + r] = pk[i].y;
            Kt[(c*4+2) * KP + r] = pk[i].z;
            Kt[(c*4+3) * KP + r] = pk[i].w;
            *(float4*)(Vs + r * VP + c * 4) = pv[i];
        }
        __syncthreads();
        if (kt + 1 < ntiles) prefetch(kt + 1);   // overlaps compute below

        float sreg[4][4];
#pragma unroll
        for (int i = 0; i < 4; i++)
#pragma unroll
            for (int j = 0; j < 4; j++) sreg[i][j] = 0.f;
#pragma unroll 8
        for (int d = 0; d < 64; d++) {
            const float4 kq = *(const float4*)(Kt + d * KP + tx * 4);
#pragma unroll
            for (int i = 0; i < 4; i++) {
                float qv = Qs[(ty * 4 + i) * QP + d];
                sreg[i][0] += qv * kq.x;
                sreg[i][1] += qv * kq.y;
                sreg[i][2] += qv * kq.z;
                sreg[i][3] += qv * kq.w;
            }
        }
#pragma unroll
        for (int i = 0; i < 4; i++) {
            const int qg = q0 + ty * 4 + i;
            if (s0 + tx*4 + 0 > qg) sreg[i][0] = -1e30f;
            if (s0 + tx*4 + 1 > qg) sreg[i][1] = -1e30f;
            if (s0 + tx*4 + 2 > qg) sreg[i][2] = -1e30f;
            if (s0 + tx*4 + 3 > qg) sreg[i][3] = -1e30f;
        }

        float frow[4];
#pragma unroll
        for (int i = 0; i < 4; i++) {
            float tmax = fmaxf(fmaxf(sreg[i][0], sreg[i][1]),
                               fmaxf(sreg[i][2], sreg[i][3]));
#pragma unroll
            for (int o = 8; o > 0; o >>= 1)
                tmax = fmaxf(tmax, __shfl_xor_sync(0xffffffffu, tmax, o));
            const float mn = fmaxf(mrow[i], tmax);
            frow[i] = __expf(mrow[i] - mn);
            mrow[i] = mn;
            float p0 = __expf(sreg[i][0] - mn);
            float p1 = __expf(sreg[i][1] - mn);
            float p2 = __expf(sreg[i][2] - mn);
            float p3 = __expf(sreg[i][3] - mn);
            float rs = p0 + p1 + p2 + p3;
#pragma unroll
            for (int o = 8; o > 0; o >>= 1)
                rs += __shfl_xor_sync(0xffffffffu, rs, o);
            lrow[i] = lrow[i] * frow[i] + rs;
            *(float4*)(Ss + (ty * 4 + i) * SP + tx * 4) = make_float4(p0, p1, p2, p3);
            acc[i][0] *= frow[i]; acc[i][1] *= frow[i];
            acc[i][2] *= frow[i]; acc[i][3] *= frow[i];
        }
        __syncthreads();

#pragma unroll 4
        for (int s = 0; s < 64; s++) {
            const float4 v4 = *(const float4*)(Vs + s * VP + tx * 4);
#pragma unroll
            for (int i = 0; i < 4; i++) {
                const float p = Ss[(ty * 4 + i) * SP + s];
                acc[i][0] += p * v4.x;
                acc[i][1] += p * v4.y;
                acc[i][2] += p * v4.z;
                acc[i][3] += p * v4.w;
            }
        }
        __syncthreads();
    }

#pragma unroll
    for (int i = 0; i < 4; i++) {
        const int q = ty * 4 + i;
        const float inv = 1.f / lrow[i];
        float v0 = acc[i][0] * inv, v1 = acc[i][1] * inv;
        float v2 = acc[i][2] * inv, v3 = acc[i][3] * inv;
        __half h0, l0, h1, l1, h2, l2, h3, l3;
        split_act(v0, h0, l0); split_act(v1, h1, l1);
        split_act(v2, h2, l2); split_act(v3, h3, l3);
        size_t base = ((size_t)((q0 + q) * BATCH + b)) * D + h * DKH + tx * 4;
        *(__half2*)(ahi + base)     = __halves2half2(h0, h1);
        *(__half2*)(ahi + base + 2) = __halves2half2(h2, h3);
        *(__half2*)(alo + base)     = __halves2half2(l0, l1);
        *(__half2*)(alo + base + 2) = __halves2half2(l2, l3);
    }
}

// ---------------- fused GRU + LN + splits (one block per token) --------------
__global__ __launch_bounds__(256)
void gru_ln_split(float* __restrict__ px, const float* __restrict__ gate,
                  const float* __restrict__ bg,
                  const float* __restrict__ g, const float* __restrict__ b,
                  __half* __restrict__ cathi, __half* __restrict__ catlo,
                  __half* __restrict__ lnhi, __half* __restrict__ lnlo,
                  float* __restrict__ outf) {
    const int n = blockIdx.x;
    const int tid = threadIdx.x;
    const float* grow = gate + (size_t)n * D3;
    float vals[4];
    float s = 0.f, sq = 0.f;
#pragma unroll
    for (int k = 0; k < 4; k++) {
        const int j = tid + k * 256;
        float gr = grow[j];
        float gz = grow[D + j];
        float gh = grow[2 * D + j];
        float r = 1.f / (1.f + __expf(-gr));
        float z = 1.f / (1.f + __expf(-(gz - bg[j])));
        float hh = tanhf(gh * r);
        float xv = px[(size_t)n * D + j];
        float v = (1.f - z) * xv + z * hh;
        px[(size_t)n * D + j] = v;
        vals[k] = v;
        __half h, l; split_act(v, h, l);
        cathi[(size_t)n * D2 + j] = h;
        catlo[(size_t)n * D2 + j] = l;
        s += v; sq += v * v;
    }
    __shared__ float rs[256], rq[256];
    rs[tid] = s; rq[tid] = sq; __syncthreads();
    for (int off = 128; off > 0; off >>= 1) {
        if (tid < off) { rs[tid] += rs[tid + off]; rq[tid] += rq[tid + off]; }
        __syncthreads();
    }
    const float mu  = rs[0] * (1.f / D);
    const float var = rq[0] * (1.f / D) - mu * mu;
    const float inv = rsqrtf(var + 1e-6f);
#pragma unroll
    for (int k = 0; k < 4; k++) {
        const int j = tid + k * 256;
        float y = (vals[k] - mu) * inv * g[j] + b[j];
        if (outf) {
            outf[(size_t)n * D + j] = y;
        } else {
            __half h, l; split_act(y, h, l);
            lnhi[(size_t)n * D + j] = h;
            lnlo[(size_t)n * D + j] = l;
        }
    }
}

// ---------------- fused GELU+PE + LN + splits (layer-0 entry) ----------------
__global__ __launch_bounds__(256)
void gelu_pe_ln_split(float* __restrict__ px, const float* __restrict__ pe,
                      const float* __restrict__ g, const float* __restrict__ b,
                      __half* __restrict__ cathi, __half* __restrict__ catlo,
                      __half* __restrict__ lnhi, __half* __restrict__ lnlo) {
    const int n = blockIdx.x;
    const int t = n >> 1;
    const int tid = threadIdx.x;
    float vals[4];
    float s = 0.f, sq = 0.f;
#pragma unroll
    for (int k = 0; k < 4; k++) {
        const int j = tid + k * 256;
        float v = gelu_exact(px[(size_t)n * D + j]) + pe[(size_t)t * D + j];
        px[(size_t)n * D + j] = v;
        vals[k] = v;
        __half h, l; split_act(v, h, l);
        cathi[(size_t)n * D2 + j] = h;
        catlo[(size_t)n * D2 + j] = l;
        s += v; sq += v * v;
    }
    __shared__ float rs[256], rq[256];
    rs[tid] = s; rq[tid] = sq; __syncthreads();
    for (int off = 128; off > 0; off >>= 1) {
        if (tid < off) { rs[tid] += rs[tid + off]; rq[tid] += rq[tid + off]; }
        __syncthreads();
    }
    const float mu  = rs[0] * (1.f / D);
    const float var = rq[0] * (1.f / D) - mu * mu;
    const float inv = rsqrtf(var + 1e-6f);
#pragma unroll
    for (int k = 0; k < 4; k++) {
        const int j = tid + k * 256;
        float y = (vals[k] - mu) * inv * g[j] + b[j];
        __half h, l; split_act(y, h, l);
        lnhi[(size_t)n * D + j] = h;
        lnlo[(size_t)n * D + j] = l;
    }
}

// ---------------- f32 -> fp16 pair splits ----------------
__global__ void cvt_split_act(const float4* __restrict__ x,
                              __half2* __restrict__ hi, __half2* __restrict__ lo,
                              int n4) {
    int i = blockIdx.x * blockDim.x + threadIdx.x;
    if (i >= n4) return;
    float4 v = x[i];
    __half h0, l0, h1, l1, h2, l2, h3, l3;
    split_act(v.x, h0, l0); split_act(v.y, h1, l1);
    split_act(v.z, h2, l2); split_act(v.w, h3, l3);
    hi[2*i]   = __halves2half2(h0, h1);
    hi[2*i+1] = __halves2half2(h2, h3);
    lo[2*i]   = __halves2half2(l0, l1);
    lo[2*i+1] = __halves2half2(l2, l3);
}

__global__ void cvt_split_wgt(const float4* __restrict__ x,
                              __half2* __restrict__ hi, __half2* __restrict__ w2,
                              int n4) {
    int i = blockIdx.x * blockDim.x + threadIdx.x;
    if (i >= n4) return;
    float4 v = x[i];
    __half h0, l0, h1, l1, h2, l2, h3, l3;
    split_wgt(v.x, h0, l0); split_wgt(v.y, h1, l1);
    split_wgt(v.z, h2, l2); split_wgt(v.w, h3, l3);
    hi[2*i]   = __halves2half2(h0, h1);
    hi[2*i+1] = __halves2half2(h2, h3);
    w2[2*i]   = __halves2half2(l0, l1);
    w2[2*i+1] = __halves2half2(l2, l3);
}

// ---------------- driver ----------------
extern "C" void kernel_launch(void* const* d_in, const int* in_sizes, int n_in,
                              void* d_out, int out_size) {
    const float* x_in  = (const float*)d_in[0];
    const float* pe    = (const float*)d_in[1];
    const float* in_w  = (const float*)d_in[2];
    const float* in_b  = (const float*)d_in[3];
    const float* qkv_w = (const float*)d_in[4];
    const float* out_w = (const float*)d_in[5];
    const float* out_b = (const float*)d_in[6];
    const float* ln1_g = (const float*)d_in[7];
    const float* ln1_b = (const float*)d_in[8];
    const float* ln2_g = (const float*)d_in[9];
    const float* ln2_b = (const float*)d_in[10];
    const float* ff_w1 = (const float*)d_in[11];
    const float* ff_b1 = (const float*)d_in[12];
    const float* ff_w2 = (const float*)d_in[13];
    const float* ff_b2 = (const float*)d_in[14];
    const float* g1_w  = (const float*)d_in[15];
    const float* g1_bg = (const float*)d_in[16];
    const float* g2_w  = (const float*)d_in[17];
    const float* g2_bg = (const float*)d_in[18];
    const float* on_g  = (const float*)d_in[19];
    const float* on_b  = (const float*)d_in[20];

    float *px, *pqkv, *pgate;
    __half *chi, *clo, *lhi, *llo, *phi, *plo, *fhi, *flo, *xhi, *xlo;
    __half *w_in_h, *w_in_l, *w_qkv_h, *w_qkv_l, *w_out_h, *w_out_l;
    __half *w_f1_h, *w_f1_l, *w_f2_h, *w_f2_l, *w_g1_h, *w_g1_l, *w_g2_h, *w_g2_l;
    cudaGetSymbolAddress((void**)&px,    g_x);
    cudaGetSymbolAddress((void**)&pqkv,  g_qkv);
    cudaGetSymbolAddress((void**)&pgate, g_gate);
    cudaGetSymbolAddress((void**)&chi,   g_chi);  cudaGetSymbolAddress((void**)&clo,   g_clo);
    cudaGetSymbolAddress((void**)&lhi,   g_lhi);  cudaGetSymbolAddress((void**)&llo,   g_llo);
    cudaGetSymbolAddress((void**)&phi,   g_phi);  cudaGetSymbolAddress((void**)&plo,   g_plo);
    cudaGetSymbolAddress((void**)&fhi,   g_fhi);  cudaGetSymbolAddress((void**)&flo,   g_flo);
    cudaGetSymbolAddress((void**)&xhi,   g_xhi);  cudaGetSymbolAddress((void**)&xlo,   g_xlo);
    cudaGetSymbolAddress((void**)&w_in_h,  wb_in_hi);  cudaGetSymbolAddress((void**)&w_in_l,  wb_in_lo);
    cudaGetSymbolAddress((void**)&w_qkv_h, wb_qkv_hi); cudaGetSymbolAddress((void**)&w_qkv_l, wb_qkv_lo);
    cudaGetSymbolAddress((void**)&w_out_h, wb_out_hi); cudaGetSymbolAddress((void**)&w_out_l, wb_out_lo);
    cudaGetSymbolAddress((void**)&w_f1_h,  wb_f1_hi);  cudaGetSymbolAddress((void**)&w_f1_l,  wb_f1_lo);
    cudaGetSymbolAddress((void**)&w_f2_h,  wb_f2_hi);  cudaGetSymbolAddress((void**)&w_f2_l,  wb_f2_lo);
    cudaGetSymbolAddress((void**)&w_g1_h,  wb_g1_hi);  cudaGetSymbolAddress((void**)&w_g1_l,  wb_g1_lo);
    cudaGetSymbolAddress((void**)&w_g2_h,  wb_g2_hi);  cudaGetSymbolAddress((void**)&w_g2_l,  wb_g2_lo);

    cudaFuncSetAttribute(gemm_mma, cudaFuncAttributeMaxDynamicSharedMemorySize, SMEM_BYTES);
    cudaFuncSetAttribute(attn_flash, cudaFuncAttributeMaxDynamicSharedMemorySize, ATTN_SMEM);

    int nsm = 148;
    cudaDeviceGetAttribute(&nsm, cudaDevAttrMultiProcessorCount, 0);

    const int EW = 256;
    auto cvtgrid = [](int n) { return (n / 4 + 255) / 256; };

    cvt_split_wgt<<<cvtgrid(D*D),        EW>>>((const float4*)in_w,  (__half2*)w_in_h,  (__half2*)w_in_l,  D*D/4);
    cvt_split_wgt<<<cvtgrid(LNUM*D3*D),  EW>>>((const float4*)qkv_w, (__half2*)w_qkv_h, (__half2*)w_qkv_l, LNUM*D3*D/4);
    cvt_split_wgt<<<cvtgrid(LNUM*D*D),   EW>>>((const float4*)out_w, (__half2*)w_out_h, (__half2*)w_out_l, LNUM*D*D/4);
    cvt_split_wgt<<<cvtgrid(LNUM*FFD*D), EW>>>((const float4*)ff_w1, (__half2*)w_f1_h,  (__half2*)w_f1_l,  LNUM*FFD*D/4);
    cvt_split_wgt<<<cvtgrid(LNUM*D*FFD), EW>>>((const float4*)ff_w2, (__half2*)w_f2_h,  (__half2*)w_f2_l,  LNUM*D*FFD/4);
    cvt_split_wgt<<<cvtgrid(LNUM*D3*D2), EW>>>((const float4*)g1_w,  (__half2*)w_g1_h,  (__half2*)w_g1_l,  LNUM*D3*D2/4);
    cvt_split_wgt<<<cvtgrid(LNUM*D3*D2), EW>>>((const float4*)g2_w,  (__half2*)w_g2_h,  (__half2*)w_g2_l,  LNUM*D3*D2/4);
    cvt_split_act<<<cvtgrid(NTOK*D),     EW>>>((const float4*)x_in,  (__half2*)xhi,     (__half2*)xlo,     NTOK*D/4);

    const int gxD  = D   / 128, ntD  = gxD  * (NTOK / 128);
    const int gxD3 = D3  / 128, ntD3 = gxD3 * (NTOK / 128);
    const int gxFF = FFD / 128, ntFF = gxFF * (NTOK / 128);
    const int cD   = ntD  < nsm ? ntD  : nsm;
    const int cD3  = ntD3 < nsm ? ntD3 : nsm;
    const int cFF  = ntFF < nsm ? ntFF : nsm;

    gemm_mma<<<cD, 256, SMEM_BYTES>>>(xhi, xlo, D, w_in_h, w_in_l, in_b, px, 0, 0, D, D, 0, gxD, ntD);
    gelu_pe_ln_split<<<NTOK, 256>>>(px, pe, ln1_g, ln1_b, chi, clo, lhi, llo);

    for (int l = 0; l < LNUM; l++) {
        const __half* qwh = w_qkv_h + (size_t)l*D3*D;  const __half* qwl = w_qkv_l + (size_t)l*D3*D;
        const __half* owh = w_out_h + (size_t)l*D*D;   const __half* owl = w_out_l + (size_t)l*D*D;
        const __half* f1h = w_f1_h  + (size_t)l*FFD*D; const __half* f1l = w_f1_l  + (size_t)l*FFD*D;
        const __half* f2h = w_f2_h  + (size_t)l*D*FFD; const __half* f2l = w_f2_l  + (size_t)l*D*FFD;
        const __half* g1h = w_g1_h  + (size_t)l*D3*D2; const __half* g1l = w_g1_l  + (size_t)l*D3*D2;
        const __half* g2h = w_g2_h  + (size_t)l*D3*D2; const __half* g2l = w_g2_l  + (size_t)l*D3*D2;
        const float* ob  = out_b + (size_t)l*D;
        const float* l2g = ln2_g + (size_t)l*D;  const float* l2b = ln2_b + (size_t)l*D;
        const float* fb1 = ff_b1 + (size_t)l*FFD;
        const float* fb2 = ff_b2 + (size_t)l*D;
        const float* gb1 = g1_bg + (size_t)l*D;
        const float* gb2 = g2_bg + (size_t)l*D;
        const float* ng = (l + 1 < LNUM) ? ln1_g + (size_t)(l+1)*D : on_g;
        const float* nb = (l + 1 < LNUM) ? ln1_b + (size_t)(l+1)*D : on_b;
        float* fout = (l + 1 < LNUM) ? nullptr : (float*)d_out;

        // attention block
        gemm_mma<<<cD3, 256, SMEM_BYTES>>>(lhi, llo, D, qwh, qwl, nullptr, pqkv, 0, 0, D3, D, 0, gxD3, ntD3);
        attn_flash<<<dim3(TT/QTILE, BATCH*H), 256, ATTN_SMEM>>>(pqkv, phi, plo);
        gemm_mma<<<cD, 256, SMEM_BYTES>>>(phi, plo, D, owh, owl, ob, 0, chi + D, clo + D, D2, D, 2, gxD, ntD);
        gemm_mma<<<cD3, 256, SMEM_BYTES>>>(chi, clo, D2, g1h, g1l, nullptr, pgate, 0, 0, D3, D2, 0, gxD3, ntD3);
        gru_ln_split<<<NTOK, 256>>>(px, pgate, gb1, l2g, l2b, chi, clo, lhi, llo, nullptr);

        // feed-forward block
        gemm_mma<<<cFF, 256, SMEM_BYTES>>>(lhi, llo, D, f1h, f1l, fb1, 0, fhi, flo, FFD, D, 1, gxFF, ntFF);
        gemm_mma<<<cD, 256, SMEM_BYTES>>>(fhi, flo, FFD, f2h, f2l, fb2, 0, chi + D, clo + D, D2, FFD, 2, gxD, ntD);
        gemm_mma<<<cD3, 256, SMEM_BYTES>>>(chi, clo, D2, g2h, g2l, nullptr, pgate, 0, 0, D3, D2, 0, gxD3, ntD3);
        gru_ln_split<<<NTOK, 256>>>(px, pgate, gb2, ng, nb, chi, clo, lhi, llo, fout);
    }
}

// round 14
// speedup vs baseline: 1.0954x; 1.0029x over previous
#include <cuda_runtime.h>
#include <cuda_fp16.h>
#include <math.h>
#include <stdint.h>

// ---------------- problem constants ----------------
#define LNUM  6
#define D     1024
#define H     16
#define DKH   64
#define FFD   4096
#define TT    1024
#define BATCH 2
#define NTOK  2048
#define D3    3072
#define D2    2048
#define ATT_SCALE 0.125f
#define SCL   0.015625f        // 2^-6
#define SCLI  64.0f            // 2^6

#define SWZ(o) ((o) ^ (((o) >> 3) & 0x70))

// ---------------- scratch (device globals; no allocs allowed) ----------------
__device__ float g_x   [NTOK*D];     // residual stream (f32)
__device__ float g_qkv [NTOK*D3];
__device__ float g_gate[NTOK*D3];
__device__ __half g_chi[NTOK*D2],  g_clo[NTOK*D2];   // concat [x,y] hi / A2
__device__ __half g_lhi[NTOK*D],   g_llo[NTOK*D];    // LN output hi / A2
__device__ __half g_phi[NTOK*D],   g_plo[NTOK*D];    // attn output hi / A2
__device__ __half g_fhi[NTOK*FFD], g_flo[NTOK*FFD];  // FF hidden hi / A2
__device__ __half g_xhi[NTOK*D],   g_xlo[NTOK*D];    // input x split
__device__ __half wb_in_hi [D*D],        wb_in_lo [D*D];
__device__ __half wb_qkv_hi[LNUM*D3*D],  wb_qkv_lo[LNUM*D3*D];
__device__ __half wb_out_hi[LNUM*D*D],   wb_out_lo[LNUM*D*D];
__device__ __half wb_f1_hi [LNUM*FFD*D], wb_f1_lo [LNUM*FFD*D];
__device__ __half wb_f2_hi [LNUM*D*FFD], wb_f2_lo [LNUM*D*FFD];
__device__ __half wb_g1_hi [LNUM*D3*D2], wb_g1_lo [LNUM*D3*D2];
__device__ __half wb_g2_hi [LNUM*D3*D2], wb_g2_lo [LNUM*D3*D2];

// ---------------- PTX helpers (portable: sm_80-level) ----------------
__device__ __forceinline__ uint32_t smem_u32(const void* p) {
    uint32_t a;
    asm("{ .reg .u64 t; cvta.to.shared.u64 t, %1; cvt.u32.u64 %0, t; }" : "=r"(a) : "l"(p));
    return a;
}
__device__ __forceinline__ void cp16(uint32_t d, const void* g) {
    asm volatile("cp.async.cg.shared.global [%0], [%1], 16;" :: "r"(d), "l"(g));
}
__device__ __forceinline__ void ldm_x4(uint32_t* f, uint32_t addr) {
    asm volatile("ldmatrix.sync.aligned.m8n8.x4.shared.b16 {%0,%1,%2,%3}, [%4];"
                 : "=r"(f[0]), "=r"(f[1]), "=r"(f[2]), "=r"(f[3]) : "r"(addr));
}
__device__ __forceinline__ void mma16816(float* c, const uint32_t* a, uint32_t b0, uint32_t b1) {
    asm volatile(
        "mma.sync.aligned.m16n8k16.row.col.f32.f16.f16.f32 "
        "{%0,%1,%2,%3}, {%4,%5,%6,%7}, {%8,%9}, {%0,%1,%2,%3};"
        : "+f"(c[0]), "+f"(c[1]), "+f"(c[2]), "+f"(c[3])
        : "r"(a[0]), "r"(a[1]), "r"(a[2]), "r"(a[3]), "r"(b0), "r"(b1));
}
__device__ __forceinline__ float gelu_exact(float v) { return v * normcdff(v); }

// Activation split: hi = fp16(v); A2 = fp16((v - hi) + hi*2^-6)
__device__ __forceinline__ void split_act(float v, __half& h, __half& a2) {
    h = __float2half_rn(v);
    float lo = v - __half2float(h);
    a2 = __float2half_rn(fmaf(__half2float(h), SCL, lo));
}
// Weight split: hi = fp16(w); W2 = fp16(hi + (w - hi)*2^6)
__device__ __forceinline__ void split_wgt(float w, __half& h, __half& w2) {
    h = __float2half_rn(w);
    float lo = w - __half2float(h);
    w2 = __float2half_rn(fmaf(lo, SCLI, __half2float(h)));
}
// Final combine: C = acc1*(1 - 2^-6) + acc2
__device__ __forceinline__ float combine(float a1, float a2) {
    return fmaf(a1, 1.0f - SCL, a2);
}

// ---------------- fp16 2-MMA GEMM (persistent, 2-stage — R11 proven) ---------
#define STAGE_B 65536
#define SMEM_BYTES (2*STAGE_B)

__global__ __launch_bounds__(256)
void gemm_mma(const __half* __restrict__ Ahi, const __half* __restrict__ A2p,
              int lda,
              const __half* __restrict__ Whi, const __half* __restrict__ W2p,
              const float* __restrict__ bias,
              float* __restrict__ Cf,
              __half* __restrict__ Chi, __half* __restrict__ Clo,
              int ldc, int K, int mode, int gx, int ntiles)
{
    extern __shared__ char smem[];
    const uint32_t sb = smem_u32(smem);
    const int tid  = threadIdx.x;
    const int wid  = tid >> 5;
    const int lane = tid & 31;
    const int wm   = wid >> 1;
    const int wn   = wid & 1;

    const int lr   = lane & 15;
    const int koff = (lane >> 4) << 4;
    uint32_t roffA[2], rxA[2], roffB[4], rxB[4];
#pragma unroll
    for (int i = 0; i < 2; i++) {
        int r = wm * 32 + i * 16 + lr;
        roffA[i] = r * 128; rxA[i] = (r & 7) << 4;
    }
#pragma unroll
    for (int j = 0; j < 4; j++) {
        int r = wn * 64 + j * 16 + lr;
        roffB[j] = r * 128; rxB[j] = (r & 7) << 4;
    }

    const int nch = K / 64;
    const int ldr = tid >> 3, ldc4 = tid & 7;

    auto issue = [&](int tt, int cc, int stage) {
        const int r0 = (tt / gx) * 128;
        const int c0 = (tt % gx) * 128;
        const int kbase = cc * 64;
        const uint32_t st = sb + stage * STAGE_B;
#pragma unroll
        for (int i = 0; i < 4; i++) {
            int r = ldr + i * 32;
            uint32_t off = SWZ((uint32_t)(r * 128 + ldc4 * 16));
            size_t sa = (size_t)(r0 + r) * lda + kbase + ldc4 * 8;
            size_t sw = (size_t)(c0 + r) * K   + kbase + ldc4 * 8;
            cp16(st +         off, Ahi + sa);
            cp16(st + 16384 + off, A2p + sa);
            cp16(st + 32768 + off, Whi + sw);
            cp16(st + 49152 + off, W2p + sw);
        }
        asm volatile("cp.async.commit_group;");
    };

    const int grid = (int)gridDim.x;
    int cur_stage = 0;
    issue(blockIdx.x, 0, 0);

    for (int t = blockIdx.x; t < ntiles; t += grid) {
        const int row0 = (t / gx) * 128;
        const int col0 = (t % gx) * 128;

        float acc1[2][8][4], acc2[2][8][4];
#pragma unroll
        for (int i = 0; i < 2; i++)
#pragma unroll
            for (int g = 0; g < 8; g++)
#pragma unroll
                for (int q = 0; q < 4; q++) { acc1[i][g][q] = 0.f; acc2[i][g][q] = 0.f; }

        for (int cc = 0; cc < nch; cc++) {
            asm volatile("cp.async.wait_group 0;");
            __syncthreads();
            const int nxt = cur_stage ^ 1;
            if (cc + 1 < nch)              issue(t, cc + 1, nxt);
            else if (t + grid < ntiles)    issue(t + grid, 0, nxt);

            const uint32_t AH = sb + cur_stage * STAGE_B;
            const uint32_t AL = AH + 16384;
            const uint32_t WHs = AH + 32768;
            const uint32_t WLs = AH + 49152;
#pragma unroll
            for (int ks = 0; ks < 4; ks++) {
                const uint32_t kb = ks * 32 + koff;
                uint32_t ah[2][4], a2[2][4];
#pragma unroll
                for (int i = 0; i < 2; i++) {
                    ldm_x4(ah[i], AH + roffA[i] + (kb ^ rxA[i]));
                    ldm_x4(a2[i], AL + roffA[i] + (kb ^ rxA[i]));
                }
#pragma unroll
                for (int j = 0; j < 4; j++) {
                    uint32_t bh[4], b2[4];
                    ldm_x4(bh, WHs + roffB[j] + (kb ^ rxB[j]));
                    ldm_x4(b2, WLs + roffB[j] + (kb ^ rxB[j]));
#pragma unroll
                    for (int i = 0; i < 2; i++) {
                        mma16816(acc1[i][j*2+0], ah[i], bh[0], bh[2]);
                        mma16816(acc1[i][j*2+1], ah[i], bh[1], bh[3]);
                        mma16816(acc2[i][j*2+0], a2[i], b2[0], b2[2]);
                        mma16816(acc2[i][j*2+1], a2[i], b2[1], b2[3]);
                    }
                }
            }
            cur_stage ^= 1;
        }

        const int rbase = row0 + wm * 32 + (lane >> 2);
        const int cbase = wn * 64 + (lane & 3) * 2;
#pragma unroll
        for (int i = 0; i < 2; i++) {
#pragma unroll
            for (int g = 0; g < 8; g++) {
                const int c  = cbase + g * 8;
                const int cg = col0 + c;
                const int r0 = rbase + i * 16;
                float b0 = bias ? bias[cg]     : 0.f;
                float b1 = bias ? bias[cg + 1] : 0.f;
                float v00 = combine(acc1[i][g][0], acc2[i][g][0]) + b0;
                float v01 = combine(acc1[i][g][1], acc2[i][g][1]) + b1;
                float v10 = combine(acc1[i][g][2], acc2[i][g][2]) + b0;
                float v11 = combine(acc1[i][g][3], acc2[i][g][3]) + b1;
                if (mode == 0) {
                    *(float2*)(Cf + (size_t)r0 * ldc + cg)     = make_float2(v00, v01);
                    *(float2*)(Cf + (size_t)(r0+8) * ldc + cg) = make_float2(v10, v11);
                } else {
                    if (mode == 1) {
                        v00 = gelu_exact(v00); v01 = gelu_exact(v01);
                        v10 = gelu_exact(v10); v11 = gelu_exact(v11);
                    }
                    __half h00, l00, h01, l01, h10, l10, h11, l11;
                    split_act(v00, h00, l00); split_act(v01, h01, l01);
                    split_act(v10, h10, l10); split_act(v11, h11, l11);
                    *(__half2*)(Chi + (size_t)r0 * ldc + cg)     = __halves2half2(h00, h01);
                    *(__half2*)(Chi + (size_t)(r0+8) * ldc + cg) = __halves2half2(h10, h11);
                    *(__half2*)(Clo + (size_t)r0 * ldc + cg)     = __halves2half2(l00, l01);
                    *(__half2*)(Clo + (size_t)(r0+8) * ldc + cg) = __halves2half2(l10, l11);
                }
            }
        }
    }
}

// ---------------- flash attention: QTILE=64, target 3 CTAs/SM ----------------
#define QTILE 64
#define KTILE 64
#define QP 68
#define KP 68
#define VP 68
#define SP 68
#define AQ_OFF 0
#define AK_OFF (AQ_OFF + 64*QP)
#define AV_OFF (AK_OFF + 64*KP)
#define AS_OFF (AV_OFF + 64*VP)
#define ATTN_SMEM ((AS_OFF + 64*SP) * 4)

__global__ __launch_bounds__(256, 3)
void attn_flash(const float* __restrict__ qkv,
                __half* __restrict__ ahi, __half* __restrict__ alo) {
    extern __shared__ float sm[];
    float* Qs = sm + AQ_OFF;
    float* Kt = sm + AK_OFF;
    float* Vs = sm + AV_OFF;
    float* Ss = sm + AS_OFF;

    const int tid = threadIdx.x;
    const int tx = tid & 15, ty = tid >> 4;
    const int bh = blockIdx.y;
    const int b  = bh >> 4;
    const int h  = bh & 15;
    const int qt = (int)gridDim.x - 1 - (int)blockIdx.x;   // heavy tiles first
    const int q0 = qt * QTILE;

#pragma unroll
    for (int i = 0; i < 4; i++) {
        int idx = tid + i * 256;
        int r = idx >> 4, c = idx & 15;
        float4 v = *(const float4*)(qkv + ((size_t)((q0 + r) * BATCH + b)) * D3 + h * DKH + c * 4);
        v.x *= ATT_SCALE; v.y *= ATT_SCALE; v.z *= ATT_SCALE; v.w *= ATT_SCALE;
        *(float4*)(Qs + r * QP + c * 4) = v;
    }

    float acc[4][4];
    float mrow[4], lrow[4];
#pragma unroll
    for (int i = 0; i < 4; i++) {
        mrow[i] = -1e30f; lrow[i] = 0.f;
#pragma unroll
        for (int j = 0; j < 4; j++) acc[i][j] = 0.f;
    }

    __syncthreads();

    const int ntiles = qt + 1;

    for (int kt = 0; kt < ntiles; kt++) {
        const int s0 = kt * KTILE;
#pragma unroll
        for (int i = 0; i < 4; i++) {
            int idx = tid + i * 256;
            int r = idx >> 4, c = idx & 15;
            const float* base = qkv + ((size_t)((s0 + r) * BATCH + b)) * D3 + h * DKH + c * 4;
            float4 kv = *(const float4*)(base + D);
            float4 vv = *(const float4*)(base + 2 * D);
            Kt[(c*4+0) * KP + r] = kv.x;
            Kt[(c*4+1) * KP + r] = kv.y;
            Kt[(c*4+2) * KP + r] = kv.z;
            Kt[(c*4+3) * KP + r] = kv.w;
            *(float4*)(Vs + r * VP + c * 4) = vv;
        }
        __syncthreads();

        float sreg[4][4];
#pragma unroll
        for (int i = 0; i < 4; i++)
#pragma unroll
            for (int j = 0; j < 4; j++) sreg[i][j] = 0.f;
#pragma unroll 8
        for (int d = 0; d < 64; d++) {
            const float4 kq = *(const float4*)(Kt + d * KP + tx * 4);
#pragma unroll
            for (int i = 0; i < 4; i++) {
                float qv = Qs[(ty * 4 + i) * QP + d];
                sreg[i][0] += qv * kq.x;
                sreg[i][1] += qv * kq.y;
                sreg[i][2] += qv * kq.z;
                sreg[i][3] += qv * kq.w;
            }
        }
#pragma unroll
        for (int i = 0; i < 4; i++) {
            const int qg = q0 + ty * 4 + i;
            if (s0 + tx*4 + 0 > qg) sreg[i][0] = -1e30f;
            if (s0 + tx*4 + 1 > qg) sreg[i][1] = -1e30f;
            if (s0 + tx*4 + 2 > qg) sreg[i][2] = -1e30f;
            if (s0 + tx*4 + 3 > qg) sreg[i][3] = -1e30f;
        }

        float frow[4];
#pragma unroll
        for (int i = 0; i < 4; i++) {
            float tmax = fmaxf(fmaxf(sreg[i][0], sreg[i][1]),
                               fmaxf(sreg[i][2], sreg[i][3]));
#pragma unroll
            for (int o = 8; o > 0; o >>= 1)
                tmax = fmaxf(tmax, __shfl_xor_sync(0xffffffffu, tmax, o));
            const float mn = fmaxf(mrow[i], tmax);
            frow[i] = __expf(mrow[i] - mn);
            mrow[i] = mn;
            float p0 = __expf(sreg[i][0] - mn);
            float p1 = __expf(sreg[i][1] - mn);
            float p2 = __expf(sreg[i][2] - mn);
            float p3 = __expf(sreg[i][3] - mn);
            float rs = p0 + p1 + p2 + p3;
#pragma unroll
            for (int o = 8; o > 0; o >>= 1)
                rs += __shfl_xor_sync(0xffffffffu, rs, o);
            lrow[i] = lrow[i] * frow[i] + rs;
            *(float4*)(Ss + (ty * 4 + i) * SP + tx * 4) = make_float4(p0, p1, p2, p3);
            acc[i][0] *= frow[i]; acc[i][1] *= frow[i];
            acc[i][2] *= frow[i]; acc[i][3] *= frow[i];
        }
        __syncthreads();

#pragma unroll 4
        for (int s = 0; s < 64; s++) {
            const float4 v4 = *(const float4*)(Vs + s * VP + tx * 4);
#pragma unroll
            for (int i = 0; i < 4; i++) {
                const float p = Ss[(ty * 4 + i) * SP + s];
                acc[i][0] += p * v4.x;
                acc[i][1] += p * v4.y;
                acc[i][2] += p * v4.z;
                acc[i][3] += p * v4.w;
            }
        }
        __syncthreads();
    }

#pragma unroll
    for (int i = 0; i < 4; i++) {
        const int q = ty * 4 + i;
        const float inv = 1.f / lrow[i];
        float v0 = acc[i][0] * inv, v1 = acc[i][1] * inv;
        float v2 = acc[i][2] * inv, v3 = acc[i][3] * inv;
        __half h0, l0, h1, l1, h2, l2, h3, l3;
        split_act(v0, h0, l0); split_act(v1, h1, l1);
        split_act(v2, h2, l2); split_act(v3, h3, l3);
        size_t base = ((size_t)((q0 + q) * BATCH + b)) * D + h * DKH + tx * 4;
        *(__half2*)(ahi + base)     = __halves2half2(h0, h1);
        *(__half2*)(ahi + base + 2) = __halves2half2(h2, h3);
        *(__half2*)(alo + base)     = __halves2half2(l0, l1);
        *(__half2*)(alo + base + 2) = __halves2half2(l2, l3);
    }
}

// ---------------- fused GRU + LN + splits (one block per token) --------------
__global__ __launch_bounds__(256)
void gru_ln_split(float* __restrict__ px, const float* __restrict__ gate,
                  const float* __restrict__ bg,
                  const float* __restrict__ g, const float* __restrict__ b,
                  __half* __restrict__ cathi, __half* __restrict__ catlo,
                  __half* __restrict__ lnhi, __half* __restrict__ lnlo,
                  float* __restrict__ outf) {
    const int n = blockIdx.x;
    const int tid = threadIdx.x;
    const float* grow = gate + (size_t)n * D3;
    float vals[4];
    float s = 0.f, sq = 0.f;
#pragma unroll
    for (int k = 0; k < 4; k++) {
        const int j = tid + k * 256;
        float gr = grow[j];
        float gz = grow[D + j];
        float gh = grow[2 * D + j];
        float r = 1.f / (1.f + __expf(-gr));
        float z = 1.f / (1.f + __expf(-(gz - bg[j])));
        float hh = tanhf(gh * r);
        float xv = px[(size_t)n * D + j];
        float v = (1.f - z) * xv + z * hh;
        px[(size_t)n * D + j] = v;
        vals[k] = v;
        __half h, l; split_act(v, h, l);
        cathi[(size_t)n * D2 + j] = h;
        catlo[(size_t)n * D2 + j] = l;
        s += v; sq += v * v;
    }
    __shared__ float rs[256], rq[256];
    rs[tid] = s; rq[tid] = sq; __syncthreads();
    for (int off = 128; off > 0; off >>= 1) {
        if (tid < off) { rs[tid] += rs[tid + off]; rq[tid] += rq[tid + off]; }
        __syncthreads();
    }
    const float mu  = rs[0] * (1.f / D);
    const float var = rq[0] * (1.f / D) - mu * mu;
    const float inv = rsqrtf(var + 1e-6f);
#pragma unroll
    for (int k = 0; k < 4; k++) {
        const int j = tid + k * 256;
        float y = (vals[k] - mu) * inv * g[j] + b[j];
        if (outf) {
            outf[(size_t)n * D + j] = y;
        } else {
            __half h, l; split_act(y, h, l);
            lnhi[(size_t)n * D + j] = h;
            lnlo[(size_t)n * D + j] = l;
        }
    }
}

// ---------------- fused GELU+PE + LN + splits (layer-0 entry) ----------------
__global__ __launch_bounds__(256)
void gelu_pe_ln_split(float* __restrict__ px, const float* __restrict__ pe,
                      const float* __restrict__ g, const float* __restrict__ b,
                      __half* __restrict__ cathi, __half* __restrict__ catlo,
                      __half* __restrict__ lnhi, __half* __restrict__ lnlo) {
    const int n = blockIdx.x;
    const int t = n >> 1;
    const int tid = threadIdx.x;
    float vals[4];
    float s = 0.f, sq = 0.f;
#pragma unroll
    for (int k = 0; k < 4; k++) {
        const int j = tid + k * 256;
        float v = gelu_exact(px[(size_t)n * D + j]) + pe[(size_t)t * D + j];
        px[(size_t)n * D + j] = v;
        vals[k] = v;
        __half h, l; split_act(v, h, l);
        cathi[(size_t)n * D2 + j] = h;
        catlo[(size_t)n * D2 + j] = l;
        s += v; sq += v * v;
    }
    __shared__ float rs[256], rq[256];
    rs[tid] = s; rq[tid] = sq; __syncthreads();
    for (int off = 128; off > 0; off >>= 1) {
        if (tid < off) { rs[tid] += rs[tid + off]; rq[tid] += rq[tid + off]; }
        __syncthreads();
    }
    const float mu  = rs[0] * (1.f / D);
    const float var = rq[0] * (1.f / D) - mu * mu;
    const float inv = rsqrtf(var + 1e-6f);
#pragma unroll
    for (int k = 0; k < 4; k++) {
        const int j = tid + k * 256;
        float y = (vals[k] - mu) * inv * g[j] + b[j];
        __half h, l; split_act(y, h, l);
        lnhi[(size_t)n * D + j] = h;
        lnlo[(size_t)n * D + j] = l;
    }
}

// ---------------- f32 -> fp16 pair splits ----------------
__global__ void cvt_split_act(const float4* __restrict__ x,
                              __half2* __restrict__ hi, __half2* __restrict__ lo,
                              int n4) {
    int i = blockIdx.x * blockDim.x + threadIdx.x;
    if (i >= n4) return;
    float4 v = x[i];
    __half h0, l0, h1, l1, h2, l2, h3, l3;
    split_act(v.x, h0, l0); split_act(v.y, h1, l1);
    split_act(v.z, h2, l2); split_act(v.w, h3, l3);
    hi[2*i]   = __halves2half2(h0, h1);
    hi[2*i+1] = __halves2half2(h2, h3);
    lo[2*i]   = __halves2half2(l0, l1);
    lo[2*i+1] = __halves2half2(l2, l3);
}

__global__ void cvt_split_wgt(const float4* __restrict__ x,
                              __half2* __restrict__ hi, __half2* __restrict__ w2,
                              int n4) {
    int i = blockIdx.x * blockDim.x + threadIdx.x;
    if (i >= n4) return;
    float4 v = x[i];
    __half h0, l0, h1, l1, h2, l2, h3, l3;
    split_wgt(v.x, h0, l0); split_wgt(v.y, h1, l1);
    split_wgt(v.z, h2, l2); split_wgt(v.w, h3, l3);
    hi[2*i]   = __halves2half2(h0, h1);
    hi[2*i+1] = __halves2half2(h2, h3);
    w2[2*i]   = __halves2half2(l0, l1);
    w2[2*i+1] = __halves2half2(l2, l3);
}

// ---------------- driver ----------------
extern "C" void kernel_launch(void* const* d_in, const int* in_sizes, int n_in,
                              void* d_out, int out_size) {
    const float* x_in  = (const float*)d_in[0];
    const float* pe    = (const float*)d_in[1];
    const float* in_w  = (const float*)d_in[2];
    const float* in_b  = (const float*)d_in[3];
    const float* qkv_w = (const float*)d_in[4];
    const float* out_w = (const float*)d_in[5];
    const float* out_b = (const float*)d_in[6];
    const float* ln1_g = (const float*)d_in[7];
    const float* ln1_b = (const float*)d_in[8];
    const float* ln2_g = (const float*)d_in[9];
    const float* ln2_b = (const float*)d_in[10];
    const float* ff_w1 = (const float*)d_in[11];
    const float* ff_b1 = (const float*)d_in[12];
    const float* ff_w2 = (const float*)d_in[13];
    const float* ff_b2 = (const float*)d_in[14];
    const float* g1_w  = (const float*)d_in[15];
    const float* g1_bg = (const float*)d_in[16];
    const float* g2_w  = (const float*)d_in[17];
    const float* g2_bg = (const float*)d_in[18];
    const float* on_g  = (const float*)d_in[19];
    const float* on_b  = (const float*)d_in[20];

    float *px, *pqkv, *pgate;
    __half *chi, *clo, *lhi, *llo, *phi, *plo, *fhi, *flo, *xhi, *xlo;
    __half *w_in_h, *w_in_l, *w_qkv_h, *w_qkv_l, *w_out_h, *w_out_l;
    __half *w_f1_h, *w_f1_l, *w_f2_h, *w_f2_l, *w_g1_h, *w_g1_l, *w_g2_h, *w_g2_l;
    cudaGetSymbolAddress((void**)&px,    g_x);
    cudaGetSymbolAddress((void**)&pqkv,  g_qkv);
    cudaGetSymbolAddress((void**)&pgate, g_gate);
    cudaGetSymbolAddress((void**)&chi,   g_chi);  cudaGetSymbolAddress((void**)&clo,   g_clo);
    cudaGetSymbolAddress((void**)&lhi,   g_lhi);  cudaGetSymbolAddress((void**)&llo,   g_llo);
    cudaGetSymbolAddress((void**)&phi,   g_phi);  cudaGetSymbolAddress((void**)&plo,   g_plo);
    cudaGetSymbolAddress((void**)&fhi,   g_fhi);  cudaGetSymbolAddress((void**)&flo,   g_flo);
    cudaGetSymbolAddress((void**)&xhi,   g_xhi);  cudaGetSymbolAddress((void**)&xlo,   g_xlo);
    cudaGetSymbolAddress((void**)&w_in_h,  wb_in_hi);  cudaGetSymbolAddress((void**)&w_in_l,  wb_in_lo);
    cudaGetSymbolAddress((void**)&w_qkv_h, wb_qkv_hi); cudaGetSymbolAddress((void**)&w_qkv_l, wb_qkv_lo);
    cudaGetSymbolAddress((void**)&w_out_h, wb_out_hi); cudaGetSymbolAddress((void**)&w_out_l, wb_out_lo);
    cudaGetSymbolAddress((void**)&w_f1_h,  wb_f1_hi);  cudaGetSymbolAddress((void**)&w_f1_l,  wb_f1_lo);
    cudaGetSymbolAddress((void**)&w_f2_h,  wb_f2_hi);  cudaGetSymbolAddress((void**)&w_f2_l,  wb_f2_lo);
    cudaGetSymbolAddress((void**)&w_g1_h,  wb_g1_hi);  cudaGetSymbolAddress((void**)&w_g1_l,  wb_g1_lo);
    cudaGetSymbolAddress((void**)&w_g2_h,  wb_g2_hi);  cudaGetSymbolAddress((void**)&w_g2_l,  wb_g2_lo);

    cudaFuncSetAttribute(gemm_mma, cudaFuncAttributeMaxDynamicSharedMemorySize, SMEM_BYTES);
    cudaFuncSetAttribute(attn_flash, cudaFuncAttributeMaxDynamicSharedMemorySize, ATTN_SMEM);

    int nsm = 148;
    cudaDeviceGetAttribute(&nsm, cudaDevAttrMultiProcessorCount, 0);

    const int EW = 256;
    auto cvtgrid = [](int n) { return (n / 4 + 255) / 256; };

    cvt_split_wgt<<<cvtgrid(D*D),        EW>>>((const float4*)in_w,  (__half2*)w_in_h,  (__half2*)w_in_l,  D*D/4);
    cvt_split_wgt<<<cvtgrid(LNUM*D3*D),  EW>>>((const float4*)qkv_w, (__half2*)w_qkv_h, (__half2*)w_qkv_l, LNUM*D3*D/4);
    cvt_split_wgt<<<cvtgrid(LNUM*D*D),   EW>>>((const float4*)out_w, (__half2*)w_out_h, (__half2*)w_out_l, LNUM*D*D/4);
    cvt_split_wgt<<<cvtgrid(LNUM*FFD*D), EW>>>((const float4*)ff_w1, (__half2*)w_f1_h,  (__half2*)w_f1_l,  LNUM*FFD*D/4);
    cvt_split_wgt<<<cvtgrid(LNUM*D*FFD), EW>>>((const float4*)ff_w2, (__half2*)w_f2_h,  (__half2*)w_f2_l,  LNUM*D*FFD/4);
    cvt_split_wgt<<<cvtgrid(LNUM*D3*D2), EW>>>((const float4*)g1_w,  (__half2*)w_g1_h,  (__half2*)w_g1_l,  LNUM*D3*D2/4);
    cvt_split_wgt<<<cvtgrid(LNUM*D3*D2), EW>>>((const float4*)g2_w,  (__half2*)w_g2_h,  (__half2*)w_g2_l,  LNUM*D3*D2/4);
    cvt_split_act<<<cvtgrid(NTOK*D),     EW>>>((const float4*)x_in,  (__half2*)xhi,     (__half2*)xlo,     NTOK*D/4);

    const int gxD  = D   / 128, ntD  = gxD  * (NTOK / 128);
    const int gxD3 = D3  / 128, ntD3 = gxD3 * (NTOK / 128);
    const int gxFF = FFD / 128, ntFF = gxFF * (NTOK / 128);
    const int cD   = ntD  < nsm ? ntD  : nsm;
    const int cD3  = ntD3 < nsm ? ntD3 : nsm;
    const int cFF  = ntFF < nsm ? ntFF : nsm;

    gemm_mma<<<cD, 256, SMEM_BYTES>>>(xhi, xlo, D, w_in_h, w_in_l, in_b, px, 0, 0, D, D, 0, gxD, ntD);
    gelu_pe_ln_split<<<NTOK, 256>>>(px, pe, ln1_g, ln1_b, chi, clo, lhi, llo);

    for (int l = 0; l < LNUM; l++) {
        const __half* qwh = w_qkv_h + (size_t)l*D3*D;  const __half* qwl = w_qkv_l + (size_t)l*D3*D;
        const __half* owh = w_out_h + (size_t)l*D*D;   const __half* owl = w_out_l + (size_t)l*D*D;
        const __half* f1h = w_f1_h  + (size_t)l*FFD*D; const __half* f1l = w_f1_l  + (size_t)l*FFD*D;
        const __half* f2h = w_f2_h  + (size_t)l*D*FFD; const __half* f2l = w_f2_l  + (size_t)l*D*FFD;
        const __half* g1h = w_g1_h  + (size_t)l*D3*D2; const __half* g1l = w_g1_l  + (size_t)l*D3*D2;
        const __half* g2h = w_g2_h  + (size_t)l*D3*D2; const __half* g2l = w_g2_l  + (size_t)l*D3*D2;
        const float* ob  = out_b + (size_t)l*D;
        const float* l2g = ln2_g + (size_t)l*D;  const float* l2b = ln2_b + (size_t)l*D;
        const float* fb1 = ff_b1 + (size_t)l*FFD;
        const float* fb2 = ff_b2 + (size_t)l*D;
        const float* gb1 = g1_bg + (size_t)l*D;
        const float* gb2 = g2_bg + (size_t)l*D;
        const float* ng = (l + 1 < LNUM) ? ln1_g + (size_t)(l+1)*D : on_g;
        const float* nb = (l + 1 < LNUM) ? ln1_b + (size_t)(l+1)*D : on_b;
        float* fout = (l + 1 < LNUM) ? nullptr : (float*)d_out;

        // attention block
        gemm_mma<<<cD3, 256, SMEM_BYTES>>>(lhi, llo, D, qwh, qwl, nullptr, pqkv, 0, 0, D3, D, 0, gxD3, ntD3);
        attn_flash<<<dim3(TT/QTILE, BATCH*H), 256, ATTN_SMEM>>>(pqkv, phi, plo);
        gemm_mma<<<cD, 256, SMEM_BYTES>>>(phi, plo, D, owh, owl, ob, 0, chi + D, clo + D, D2, D, 2, gxD, ntD);
        gemm_mma<<<cD3, 256, SMEM_BYTES>>>(chi, clo, D2, g1h, g1l, nullptr, pgate, 0, 0, D3, D2, 0, gxD3, ntD3);
        gru_ln_split<<<NTOK, 256>>>(px, pgate, gb1, l2g, l2b, chi, clo, lhi, llo, nullptr);

        // feed-forward block
        gemm_mma<<<cFF, 256, SMEM_BYTES>>>(lhi, llo, D, f1h, f1l, fb1, 0, fhi, flo, FFD, D, 1, gxFF, ntFF);
        gemm_mma<<<cD, 256, SMEM_BYTES>>>(fhi, flo, FFD, f2h, f2l, fb2, 0, chi + D, clo + D, D2, FFD, 2, gxD, ntD);
        gemm_mma<<<cD3, 256, SMEM_BYTES>>>(chi, clo, D2, g2h, g2l, nullptr, pgate, 0, 0, D3, D2, 0, gxD3, ntD3);
        gru_ln_split<<<NTOK, 256>>>(px, pgate, gb2, ng, nb, chi, clo, lhi, llo, fout);
    }
}

// round 15
// speedup vs baseline: 1.1220x; 1.0243x over previous
#include <cuda_runtime.h>
#include <cuda_fp16.h>
#include <math.h>
#include <stdint.h>

// ---------------- problem constants ----------------
#define LNUM  6
#define D     1024
#define H     16
#define DKH   64
#define FFD   4096
#define TT    1024
#define BATCH 2
#define NTOK  2048
#define D3    3072
#define D2    2048
#define ATT_SCALE 0.125f
#define SCL   0.015625f        // 2^-6
#define SCLI  64.0f            // 2^6

#define SWZ(o) ((o) ^ (((o) >> 3) & 0x70))

// ---------------- scratch (device globals; no allocs allowed) ----------------
__device__ float g_x   [NTOK*D];     // residual stream (f32)
__device__ float g_qkv [NTOK*D3];
__device__ float g_gate[NTOK*D3];
__device__ __half g_chi[NTOK*D2],  g_clo[NTOK*D2];   // concat [x,y] hi / A2
__device__ __half g_lhi[NTOK*D],   g_llo[NTOK*D];    // LN output hi / A2
__device__ __half g_phi[NTOK*D],   g_plo[NTOK*D];    // attn output hi / A2
__device__ __half g_fhi[NTOK*FFD], g_flo[NTOK*FFD];  // FF hidden hi / A2
__device__ __half g_xhi[NTOK*D],   g_xlo[NTOK*D];    // input x split
__device__ __half wb_in_hi [D*D],        wb_in_lo [D*D];
__device__ __half wb_qkv_hi[LNUM*D3*D],  wb_qkv_lo[LNUM*D3*D];
__device__ __half wb_out_hi[LNUM*D*D],   wb_out_lo[LNUM*D*D];
__device__ __half wb_f1_hi [LNUM*FFD*D], wb_f1_lo [LNUM*FFD*D];
__device__ __half wb_f2_hi [LNUM*D*FFD], wb_f2_lo [LNUM*D*FFD];
__device__ __half wb_g1_hi [LNUM*D3*D2], wb_g1_lo [LNUM*D3*D2];
__device__ __half wb_g2_hi [LNUM*D3*D2], wb_g2_lo [LNUM*D3*D2];

// ---------------- PTX helpers (portable: sm_80-level) ----------------
__device__ __forceinline__ uint32_t smem_u32(const void* p) {
    uint32_t a;
    asm("{ .reg .u64 t; cvta.to.shared.u64 t, %1; cvt.u32.u64 %0, t; }" : "=r"(a) : "l"(p));
    return a;
}
__device__ __forceinline__ void cp16(uint32_t d, const void* g) {
    asm volatile("cp.async.cg.shared.global [%0], [%1], 16;" :: "r"(d), "l"(g));
}
__device__ __forceinline__ void ldm_x4(uint32_t* f, uint32_t addr) {
    asm volatile("ldmatrix.sync.aligned.m8n8.x4.shared.b16 {%0,%1,%2,%3}, [%4];"
                 : "=r"(f[0]), "=r"(f[1]), "=r"(f[2]), "=r"(f[3]) : "r"(addr));
}
__device__ __forceinline__ void mma16816(float* c, const uint32_t* a, uint32_t b0, uint32_t b1) {
    asm volatile(
        "mma.sync.aligned.m16n8k16.row.col.f32.f16.f16.f32 "
        "{%0,%1,%2,%3}, {%4,%5,%6,%7}, {%8,%9}, {%0,%1,%2,%3};"
        : "+f"(c[0]), "+f"(c[1]), "+f"(c[2]), "+f"(c[3])
        : "r"(a[0]), "r"(a[1]), "r"(a[2]), "r"(a[3]), "r"(b0), "r"(b1));
}
__device__ __forceinline__ float gelu_exact(float v) { return v * normcdff(v); }

// Activation split: hi = fp16(v); A2 = fp16((v - hi) + hi*2^-6)
__device__ __forceinline__ void split_act(float v, __half& h, __half& a2) {
    h = __float2half_rn(v);
    float lo = v - __half2float(h);
    a2 = __float2half_rn(fmaf(__half2float(h), SCL, lo));
}
// Weight split: hi = fp16(w); W2 = fp16(hi + (w - hi)*2^6)
__device__ __forceinline__ void split_wgt(float w, __half& h, __half& w2) {
    h = __float2half_rn(w);
    float lo = w - __half2float(h);
    w2 = __float2half_rn(fmaf(lo, SCLI, __half2float(h)));
}
// Final combine: C = acc1*(1 - 2^-6) + acc2
__device__ __forceinline__ float combine(float a1, float a2) {
    return fmaf(a1, 1.0f - SCL, a2);
}

// ---------------- fp16 2-MMA GEMM (persistent, 2-stage — R11 proven) ---------
#define STAGE_B 65536
#define SMEM_BYTES (2*STAGE_B)

__global__ __launch_bounds__(256)
void gemm_mma(const __half* __restrict__ Ahi, const __half* __restrict__ A2p,
              int lda,
              const __half* __restrict__ Whi, const __half* __restrict__ W2p,
              const float* __restrict__ bias,
              float* __restrict__ Cf,
              __half* __restrict__ Chi, __half* __restrict__ Clo,
              int ldc, int K, int mode, int gx, int ntiles)
{
    extern __shared__ char smem[];
    const uint32_t sb = smem_u32(smem);
    const int tid  = threadIdx.x;
    const int wid  = tid >> 5;
    const int lane = tid & 31;
    const int wm   = wid >> 1;
    const int wn   = wid & 1;

    const int lr   = lane & 15;
    const int koff = (lane >> 4) << 4;
    uint32_t roffA[2], rxA[2], roffB[4], rxB[4];
#pragma unroll
    for (int i = 0; i < 2; i++) {
        int r = wm * 32 + i * 16 + lr;
        roffA[i] = r * 128; rxA[i] = (r & 7) << 4;
    }
#pragma unroll
    for (int j = 0; j < 4; j++) {
        int r = wn * 64 + j * 16 + lr;
        roffB[j] = r * 128; rxB[j] = (r & 7) << 4;
    }

    const int nch = K / 64;
    const int ldr = tid >> 3, ldc4 = tid & 7;

    auto issue = [&](int tt, int cc, int stage) {
        const int r0 = (tt / gx) * 128;
        const int c0 = (tt % gx) * 128;
        const int kbase = cc * 64;
        const uint32_t st = sb + stage * STAGE_B;
#pragma unroll
        for (int i = 0; i < 4; i++) {
            int r = ldr + i * 32;
            uint32_t off = SWZ((uint32_t)(r * 128 + ldc4 * 16));
            size_t sa = (size_t)(r0 + r) * lda + kbase + ldc4 * 8;
            size_t sw = (size_t)(c0 + r) * K   + kbase + ldc4 * 8;
            cp16(st +         off, Ahi + sa);
            cp16(st + 16384 + off, A2p + sa);
            cp16(st + 32768 + off, Whi + sw);
            cp16(st + 49152 + off, W2p + sw);
        }
        asm volatile("cp.async.commit_group;");
    };

    const int grid = (int)gridDim.x;
    int cur_stage = 0;
    issue(blockIdx.x, 0, 0);

    for (int t = blockIdx.x; t < ntiles; t += grid) {
        const int row0 = (t / gx) * 128;
        const int col0 = (t % gx) * 128;

        float acc1[2][8][4], acc2[2][8][4];
#pragma unroll
        for (int i = 0; i < 2; i++)
#pragma unroll
            for (int g = 0; g < 8; g++)
#pragma unroll
                for (int q = 0; q < 4; q++) { acc1[i][g][q] = 0.f; acc2[i][g][q] = 0.f; }

        for (int cc = 0; cc < nch; cc++) {
            asm volatile("cp.async.wait_group 0;");
            __syncthreads();
            const int nxt = cur_stage ^ 1;
            if (cc + 1 < nch)              issue(t, cc + 1, nxt);
            else if (t + grid < ntiles)    issue(t + grid, 0, nxt);

            const uint32_t AH = sb + cur_stage * STAGE_B;
            const uint32_t AL = AH + 16384;
            const uint32_t WHs = AH + 32768;
            const uint32_t WLs = AH + 49152;
#pragma unroll
            for (int ks = 0; ks < 4; ks++) {
                const uint32_t kb = ks * 32 + koff;
                uint32_t ah[2][4], a2[2][4];
#pragma unroll
                for (int i = 0; i < 2; i++) {
                    ldm_x4(ah[i], AH + roffA[i] + (kb ^ rxA[i]));
                    ldm_x4(a2[i], AL + roffA[i] + (kb ^ rxA[i]));
                }
#pragma unroll
                for (int j = 0; j < 4; j++) {
                    uint32_t bh[4], b2[4];
                    ldm_x4(bh, WHs + roffB[j] + (kb ^ rxB[j]));
                    ldm_x4(b2, WLs + roffB[j] + (kb ^ rxB[j]));
#pragma unroll
                    for (int i = 0; i < 2; i++) {
                        mma16816(acc1[i][j*2+0], ah[i], bh[0], bh[2]);
                        mma16816(acc1[i][j*2+1], ah[i], bh[1], bh[3]);
                        mma16816(acc2[i][j*2+0], a2[i], b2[0], b2[2]);
                        mma16816(acc2[i][j*2+1], a2[i], b2[1], b2[3]);
                    }
                }
            }
            cur_stage ^= 1;
        }

        const int rbase = row0 + wm * 32 + (lane >> 2);
        const int cbase = wn * 64 + (lane & 3) * 2;
#pragma unroll
        for (int i = 0; i < 2; i++) {
#pragma unroll
            for (int g = 0; g < 8; g++) {
                const int c  = cbase + g * 8;
                const int cg = col0 + c;
                const int r0 = rbase + i * 16;
                float b0 = bias ? bias[cg]     : 0.f;
                float b1 = bias ? bias[cg + 1] : 0.f;
                float v00 = combine(acc1[i][g][0], acc2[i][g][0]) + b0;
                float v01 = combine(acc1[i][g][1], acc2[i][g][1]) + b1;
                float v10 = combine(acc1[i][g][2], acc2[i][g][2]) + b0;
                float v11 = combine(acc1[i][g][3], acc2[i][g][3]) + b1;
                if (mode == 0) {
                    *(float2*)(Cf + (size_t)r0 * ldc + cg)     = make_float2(v00, v01);
                    *(float2*)(Cf + (size_t)(r0+8) * ldc + cg) = make_float2(v10, v11);
                } else {
                    if (mode == 1) {
                        v00 = gelu_exact(v00); v01 = gelu_exact(v01);
                        v10 = gelu_exact(v10); v11 = gelu_exact(v11);
                    }
                    __half h00, l00, h01, l01, h10, l10, h11, l11;
                    split_act(v00, h00, l00); split_act(v01, h01, l01);
                    split_act(v10, h10, l10); split_act(v11, h11, l11);
                    *(__half2*)(Chi + (size_t)r0 * ldc + cg)     = __halves2half2(h00, h01);
                    *(__half2*)(Chi + (size_t)(r0+8) * ldc + cg) = __halves2half2(h10, h11);
                    *(__half2*)(Clo + (size_t)r0 * ldc + cg)     = __halves2half2(l00, l01);
                    *(__half2*)(Clo + (size_t)(r0+8) * ldc + cg) = __halves2half2(l10, l11);
                }
            }
        }
    }
}

// ---------------- flash attention: QTILE=64, 2 CTAs/SM (R11 proven) ----------
#define QTILE 64
#define KTILE 64
#define QP 68
#define KP 68
#define VP 68
#define SP 68
#define AQ_OFF 0
#define AK_OFF (AQ_OFF + 64*QP)
#define AV_OFF (AK_OFF + 64*KP)
#define AS_OFF (AV_OFF + 64*VP)
#define ATTN_SMEM ((AS_OFF + 64*SP) * 4)

__global__ __launch_bounds__(256)
void attn_flash(const float* __restrict__ qkv,
                __half* __restrict__ ahi, __half* __restrict__ alo) {
    extern __shared__ float sm[];
    float* Qs = sm + AQ_OFF;
    float* Kt = sm + AK_OFF;
    float* Vs = sm + AV_OFF;
    float* Ss = sm + AS_OFF;

    const int tid = threadIdx.x;
    const int tx = tid & 15, ty = tid >> 4;
    const int bh = blockIdx.y;
    const int b  = bh >> 4;
    const int h  = bh & 15;
    const int qt = (int)gridDim.x - 1 - (int)blockIdx.x;   // heavy tiles first
    const int q0 = qt * QTILE;

#pragma unroll
    for (int i = 0; i < 4; i++) {
        int idx = tid + i * 256;
        int r = idx >> 4, c = idx & 15;
        float4 v = *(const float4*)(qkv + ((size_t)((q0 + r) * BATCH + b)) * D3 + h * DKH + c * 4);
        v.x *= ATT_SCALE; v.y *= ATT_SCALE; v.z *= ATT_SCALE; v.w *= ATT_SCALE;
        *(float4*)(Qs + r * QP + c * 4) = v;
    }

    float acc[4][4];
    float mrow[4], lrow[4];
#pragma unroll
    for (int i = 0; i < 4; i++) {
        mrow[i] = -1e30f; lrow[i] = 0.f;
#pragma unroll
        for (int j = 0; j < 4; j++) acc[i][j] = 0.f;
    }

    __syncthreads();

    const int ntiles = qt + 1;

    for (int kt = 0; kt < ntiles; kt++) {
        const int s0 = kt * KTILE;
#pragma unroll
        for (int i = 0; i < 4; i++) {
            int idx = tid + i * 256;
            int r = idx >> 4, c = idx & 15;
            const float* base = qkv + ((size_t)((s0 + r) * BATCH + b)) * D3 + h * DKH + c * 4;
            float4 kv = *(const float4*)(base + D);
            float4 vv = *(const float4*)(base + 2 * D);
            Kt[(c*4+0) * KP + r] = kv.x;
            Kt[(c*4+1) * KP + r] = kv.y;
            Kt[(c*4+2) * KP + r] = kv.z;
            Kt[(c*4+3) * KP + r] = kv.w;
            *(float4*)(Vs + r * VP + c * 4) = vv;
        }
        __syncthreads();

        float sreg[4][4];
#pragma unroll
        for (int i = 0; i < 4; i++)
#pragma unroll
            for (int j = 0; j < 4; j++) sreg[i][j] = 0.f;
#pragma unroll 8
        for (int d = 0; d < 64; d++) {
            const float4 kq = *(const float4*)(Kt + d * KP + tx * 4);
#pragma unroll
            for (int i = 0; i < 4; i++) {
                float qv = Qs[(ty * 4 + i) * QP + d];
                sreg[i][0] += qv * kq.x;
                sreg[i][1] += qv * kq.y;
                sreg[i][2] += qv * kq.z;
                sreg[i][3] += qv * kq.w;
            }
        }
#pragma unroll
        for (int i = 0; i < 4; i++) {
            const int qg = q0 + ty * 4 + i;
            if (s0 + tx*4 + 0 > qg) sreg[i][0] = -1e30f;
            if (s0 + tx*4 + 1 > qg) sreg[i][1] = -1e30f;
            if (s0 + tx*4 + 2 > qg) sreg[i][2] = -1e30f;
            if (s0 + tx*4 + 3 > qg) sreg[i][3] = -1e30f;
        }

        float frow[4];
#pragma unroll
        for (int i = 0; i < 4; i++) {
            float tmax = fmaxf(fmaxf(sreg[i][0], sreg[i][1]),
                               fmaxf(sreg[i][2], sreg[i][3]));
#pragma unroll
            for (int o = 8; o > 0; o >>= 1)
                tmax = fmaxf(tmax, __shfl_xor_sync(0xffffffffu, tmax, o));
            const float mn = fmaxf(mrow[i], tmax);
            frow[i] = __expf(mrow[i] - mn);
            mrow[i] = mn;
            float p0 = __expf(sreg[i][0] - mn);
            float p1 = __expf(sreg[i][1] - mn);
            float p2 = __expf(sreg[i][2] - mn);
            float p3 = __expf(sreg[i][3] - mn);
            float rs = p0 + p1 + p2 + p3;
#pragma unroll
            for (int o = 8; o > 0; o >>= 1)
                rs += __shfl_xor_sync(0xffffffffu, rs, o);
            lrow[i] = lrow[i] * frow[i] + rs;
            *(float4*)(Ss + (ty * 4 + i) * SP + tx * 4) = make_float4(p0, p1, p2, p3);
            acc[i][0] *= frow[i]; acc[i][1] *= frow[i];
            acc[i][2] *= frow[i]; acc[i][3] *= frow[i];
        }
        __syncthreads();

#pragma unroll 4
        for (int s = 0; s < 64; s++) {
            const float4 v4 = *(const float4*)(Vs + s * VP + tx * 4);
#pragma unroll
            for (int i = 0; i < 4; i++) {
                const float p = Ss[(ty * 4 + i) * SP + s];
                acc[i][0] += p * v4.x;
                acc[i][1] += p * v4.y;
                acc[i][2] += p * v4.z;
                acc[i][3] += p * v4.w;
            }
        }
        __syncthreads();
    }

#pragma unroll
    for (int i = 0; i < 4; i++) {
        const int q = ty * 4 + i;
        const float inv = 1.f / lrow[i];
        float v0 = acc[i][0] * inv, v1 = acc[i][1] * inv;
        float v2 = acc[i][2] * inv, v3 = acc[i][3] * inv;
        __half h0, l0, h1, l1, h2, l2, h3, l3;
        split_act(v0, h0, l0); split_act(v1, h1, l1);
        split_act(v2, h2, l2); split_act(v3, h3, l3);
        size_t base = ((size_t)((q0 + q) * BATCH + b)) * D + h * DKH + tx * 4;
        *(__half2*)(ahi + base)     = __halves2half2(h0, h1);
        *(__half2*)(ahi + base + 2) = __halves2half2(h2, h3);
        *(__half2*)(alo + base)     = __halves2half2(l0, l1);
        *(__half2*)(alo + base + 2) = __halves2half2(l2, l3);
    }
}

// ---------------- fused GRU + LN + splits (one block per token) --------------
__global__ __launch_bounds__(256)
void gru_ln_split(float* __restrict__ px, const float* __restrict__ gate,
                  const float* __restrict__ bg,
                  const float* __restrict__ g, const float* __restrict__ b,
                  __half* __restrict__ cathi, __half* __restrict__ catlo,
                  __half* __restrict__ lnhi, __half* __restrict__ lnlo,
                  float* __restrict__ outf) {
    const int n = blockIdx.x;
    const int tid = threadIdx.x;
    const float* grow = gate + (size_t)n * D3;
    float vals[4];
    float s = 0.f, sq = 0.f;
#pragma unroll
    for (int k = 0; k < 4; k++) {
        const int j = tid + k * 256;
        float gr = grow[j];
        float gz = grow[D + j];
        float gh = grow[2 * D + j];
        float r = 1.f / (1.f + __expf(-gr));
        float z = 1.f / (1.f + __expf(-(gz - bg[j])));
        float hh = tanhf(gh * r);
        float xv = px[(size_t)n * D + j];
        float v = (1.f - z) * xv + z * hh;
        px[(size_t)n * D + j] = v;
        vals[k] = v;
        __half h, l; split_act(v, h, l);
        cathi[(size_t)n * D2 + j] = h;
        catlo[(size_t)n * D2 + j] = l;
        s += v; sq += v * v;
    }
    __shared__ float rs[256], rq[256];
    rs[tid] = s; rq[tid] = sq; __syncthreads();
    for (int off = 128; off > 0; off >>= 1) {
        if (tid < off) { rs[tid] += rs[tid + off]; rq[tid] += rq[tid + off]; }
        __syncthreads();
    }
    const float mu  = rs[0] * (1.f / D);
    const float var = rq[0] * (1.f / D) - mu * mu;
    const float inv = rsqrtf(var + 1e-6f);
#pragma unroll
    for (int k = 0; k < 4; k++) {
        const int j = tid + k * 256;
        float y = (vals[k] - mu) * inv * g[j] + b[j];
        if (outf) {
            outf[(size_t)n * D + j] = y;
        } else {
            __half h, l; split_act(y, h, l);
            lnhi[(size_t)n * D + j] = h;
            lnlo[(size_t)n * D + j] = l;
        }
    }
}

// ---------------- fused GELU+PE + LN + splits (layer-0 entry) ----------------
__global__ __launch_bounds__(256)
void gelu_pe_ln_split(float* __restrict__ px, const float* __restrict__ pe,
                      const float* __restrict__ g, const float* __restrict__ b,
                      __half* __restrict__ cathi, __half* __restrict__ catlo,
                      __half* __restrict__ lnhi, __half* __restrict__ lnlo) {
    const int n = blockIdx.x;
    const int t = n >> 1;
    const int tid = threadIdx.x;
    float vals[4];
    float s = 0.f, sq = 0.f;
#pragma unroll
    for (int k = 0; k < 4; k++) {
        const int j = tid + k * 256;
        float v = gelu_exact(px[(size_t)n * D + j]) + pe[(size_t)t * D + j];
        px[(size_t)n * D + j] = v;
        vals[k] = v;
        __half h, l; split_act(v, h, l);
        cathi[(size_t)n * D2 + j] = h;
        catlo[(size_t)n * D2 + j] = l;
        s += v; sq += v * v;
    }
    __shared__ float rs[256], rq[256];
    rs[tid] = s; rq[tid] = sq; __syncthreads();
    for (int off = 128; off > 0; off >>= 1) {
        if (tid < off) { rs[tid] += rs[tid + off]; rq[tid] += rq[tid + off]; }
        __syncthreads();
    }
    const float mu  = rs[0] * (1.f / D);
    const float var = rq[0] * (1.f / D) - mu * mu;
    const float inv = rsqrtf(var + 1e-6f);
#pragma unroll
    for (int k = 0; k < 4; k++) {
        const int j = tid + k * 256;
        float y = (vals[k] - mu) * inv * g[j] + b[j];
        __half h, l; split_act(y, h, l);
        lnhi[(size_t)n * D + j] = h;
        lnlo[(size_t)n * D + j] = l;
    }
}

// ---------------- f32 -> fp16 pair splits ----------------
__global__ void cvt_split_act(const float4* __restrict__ x,
                              __half2* __restrict__ hi, __half2* __restrict__ lo,
                              int n4) {
    int i = blockIdx.x * blockDim.x + threadIdx.x;
    if (i >= n4) return;
    float4 v = x[i];
    __half h0, l0, h1, l1, h2, l2, h3, l3;
    split_act(v.x, h0, l0); split_act(v.y, h1, l1);
    split_act(v.z, h2, l2); split_act(v.w, h3, l3);
    hi[2*i]   = __halves2half2(h0, h1);
    hi[2*i+1] = __halves2half2(h2, h3);
    lo[2*i]   = __halves2half2(l0, l1);
    lo[2*i+1] = __halves2half2(l2, l3);
}

__global__ void cvt_split_wgt(const float4* __restrict__ x,
                              __half2* __restrict__ hi, __half2* __restrict__ w2,
                              int n4) {
    int i = blockIdx.x * blockDim.x + threadIdx.x;
    if (i >= n4) return;
    float4 v = x[i];
    __half h0, l0, h1, l1, h2, l2, h3, l3;
    split_wgt(v.x, h0, l0); split_wgt(v.y, h1, l1);
    split_wgt(v.z, h2, l2); split_wgt(v.w, h3, l3);
    hi[2*i]   = __halves2half2(h0, h1);
    hi[2*i+1] = __halves2half2(h2, h3);
    w2[2*i]   = __halves2half2(l0, l1);
    w2[2*i+1] = __halves2half2(l2, l3);
}

// ---------------- driver ----------------
extern "C" void kernel_launch(void* const* d_in, const int* in_sizes, int n_in,
                              void* d_out, int out_size) {
    const float* x_in  = (const float*)d_in[0];
    const float* pe    = (const float*)d_in[1];
    const float* in_w  = (const float*)d_in[2];
    const float* in_b  = (const float*)d_in[3];
    const float* qkv_w = (const float*)d_in[4];
    const float* out_w = (const float*)d_in[5];
    const float* out_b = (const float*)d_in[6];
    const float* ln1_g = (const float*)d_in[7];
    const float* ln1_b = (const float*)d_in[8];
    const float* ln2_g = (const float*)d_in[9];
    const float* ln2_b = (const float*)d_in[10];
    const float* ff_w1 = (const float*)d_in[11];
    const float* ff_b1 = (const float*)d_in[12];
    const float* ff_w2 = (const float*)d_in[13];
    const float* ff_b2 = (const float*)d_in[14];
    const float* g1_w  = (const float*)d_in[15];
    const float* g1_bg = (const float*)d_in[16];
    const float* g2_w  = (const float*)d_in[17];
    const float* g2_bg = (const float*)d_in[18];
    const float* on_g  = (const float*)d_in[19];
    const float* on_b  = (const float*)d_in[20];

    float *px, *pqkv, *pgate;
    __half *chi, *clo, *lhi, *llo, *phi, *plo, *fhi, *flo, *xhi, *xlo;
    __half *w_in_h, *w_in_l, *w_qkv_h, *w_qkv_l, *w_out_h, *w_out_l;
    __half *w_f1_h, *w_f1_l, *w_f2_h, *w_f2_l, *w_g1_h, *w_g1_l, *w_g2_h, *w_g2_l;
    cudaGetSymbolAddress((void**)&px,    g_x);
    cudaGetSymbolAddress((void**)&pqkv,  g_qkv);
    cudaGetSymbolAddress((void**)&pgate, g_gate);
    cudaGetSymbolAddress((void**)&chi,   g_chi);  cudaGetSymbolAddress((void**)&clo,   g_clo);
    cudaGetSymbolAddress((void**)&lhi,   g_lhi);  cudaGetSymbolAddress((void**)&llo,   g_llo);
    cudaGetSymbolAddress((void**)&phi,   g_phi);  cudaGetSymbolAddress((void**)&plo,   g_plo);
    cudaGetSymbolAddress((void**)&fhi,   g_fhi);  cudaGetSymbolAddress((void**)&flo,   g_flo);
    cudaGetSymbolAddress((void**)&xhi,   g_xhi);  cudaGetSymbolAddress((void**)&xlo,   g_xlo);
    cudaGetSymbolAddress((void**)&w_in_h,  wb_in_hi);  cudaGetSymbolAddress((void**)&w_in_l,  wb_in_lo);
    cudaGetSymbolAddress((void**)&w_qkv_h, wb_qkv_hi); cudaGetSymbolAddress((void**)&w_qkv_l, wb_qkv_lo);
    cudaGetSymbolAddress((void**)&w_out_h, wb_out_hi); cudaGetSymbolAddress((void**)&w_out_l, wb_out_lo);
    cudaGetSymbolAddress((void**)&w_f1_h,  wb_f1_hi);  cudaGetSymbolAddress((void**)&w_f1_l,  wb_f1_lo);
    cudaGetSymbolAddress((void**)&w_f2_h,  wb_f2_hi);  cudaGetSymbolAddress((void**)&w_f2_l,  wb_f2_lo);
    cudaGetSymbolAddress((void**)&w_g1_h,  wb_g1_hi);  cudaGetSymbolAddress((void**)&w_g1_l,  wb_g1_lo);
    cudaGetSymbolAddress((void**)&w_g2_h,  wb_g2_hi);  cudaGetSymbolAddress((void**)&w_g2_l,  wb_g2_lo);

    cudaFuncSetAttribute(gemm_mma, cudaFuncAttributeMaxDynamicSharedMemorySize, SMEM_BYTES);
    cudaFuncSetAttribute(attn_flash, cudaFuncAttributeMaxDynamicSharedMemorySize, ATTN_SMEM);

    int nsm = 148;
    cudaDeviceGetAttribute(&nsm, cudaDevAttrMultiProcessorCount, 0);

    const int EW = 256;
    auto cvtgrid = [](int n) { return (n / 4 + 255) / 256; };

    // ---- side stream for weight splits (fork/join via events; capture-safe) ----
    cudaStream_t s2;
    cudaStreamCreate(&s2);
    cudaEvent_t evf, evl[LNUM];
    cudaEventCreateWithFlags(&evf, cudaEventDisableTiming);
    for (int l = 0; l < LNUM; l++) cudaEventCreateWithFlags(&evl[l], cudaEventDisableTiming);

    // main stream: only what the prologue needs
    cvt_split_wgt<<<cvtgrid(D*D),    EW>>>((const float4*)in_w, (__half2*)w_in_h, (__half2*)w_in_l, D*D/4);
    cvt_split_act<<<cvtgrid(NTOK*D), EW>>>((const float4*)x_in, (__half2*)xhi,    (__half2*)xlo,    NTOK*D/4);
    cudaEventRecord(evf, 0);
    cudaStreamWaitEvent(s2, evf, 0);

    // side stream: per-layer weight splits, event after each layer's group
    for (int l = 0; l < LNUM; l++) {
        cvt_split_wgt<<<cvtgrid(D3*D),  EW, 0, s2>>>((const float4*)(qkv_w + (size_t)l*D3*D),  (__half2*)(w_qkv_h + (size_t)l*D3*D),  (__half2*)(w_qkv_l + (size_t)l*D3*D),  D3*D/4);
        cvt_split_wgt<<<cvtgrid(D*D),   EW, 0, s2>>>((const float4*)(out_w + (size_t)l*D*D),   (__half2*)(w_out_h + (size_t)l*D*D),   (__half2*)(w_out_l + (size_t)l*D*D),   D*D/4);
        cvt_split_wgt<<<cvtgrid(D3*D2), EW, 0, s2>>>((const float4*)(g1_w  + (size_t)l*D3*D2), (__half2*)(w_g1_h  + (size_t)l*D3*D2), (__half2*)(w_g1_l  + (size_t)l*D3*D2), D3*D2/4);
        cvt_split_wgt<<<cvtgrid(FFD*D), EW, 0, s2>>>((const float4*)(ff_w1 + (size_t)l*FFD*D), (__half2*)(w_f1_h  + (size_t)l*FFD*D), (__half2*)(w_f1_l  + (size_t)l*FFD*D), FFD*D/4);
        cvt_split_wgt<<<cvtgrid(D*FFD), EW, 0, s2>>>((const float4*)(ff_w2 + (size_t)l*D*FFD), (__half2*)(w_f2_h  + (size_t)l*D*FFD), (__half2*)(w_f2_l  + (size_t)l*D*FFD), D*FFD/4);
        cvt_split_wgt<<<cvtgrid(D3*D2), EW, 0, s2>>>((const float4*)(g2_w  + (size_t)l*D3*D2), (__half2*)(w_g2_h  + (size_t)l*D3*D2), (__half2*)(w_g2_l  + (size_t)l*D3*D2), D3*D2/4);
        cudaEventRecord(evl[l], s2);
    }

    const int gxD  = D   / 128, ntD  = gxD  * (NTOK / 128);
    const int gxD3 = D3  / 128, ntD3 = gxD3 * (NTOK / 128);
    const int gxFF = FFD / 128, ntFF = gxFF * (NTOK / 128);
    const int cD   = ntD  < nsm ? ntD  : nsm;
    const int cD3  = ntD3 < nsm ? ntD3 : nsm;
    const int cFF  = ntFF < nsm ? ntFF : nsm;

    // main stream prologue (overlaps with side-stream splits)
    gemm_mma<<<cD, 256, SMEM_BYTES>>>(xhi, xlo, D, w_in_h, w_in_l, in_b, px, 0, 0, D, D, 0, gxD, ntD);
    gelu_pe_ln_split<<<NTOK, 256>>>(px, pe, ln1_g, ln1_b, chi, clo, lhi, llo);

    for (int l = 0; l < LNUM; l++) {
        const __half* qwh = w_qkv_h + (size_t)l*D3*D;  const __half* qwl = w_qkv_l + (size_t)l*D3*D;
        const __half* owh = w_out_h + (size_t)l*D*D;   const __half* owl = w_out_l + (size_t)l*D*D;
        const __half* f1h = w_f1_h  + (size_t)l*FFD*D; const __half* f1l = w_f1_l  + (size_t)l*FFD*D;
        const __half* f2h = w_f2_h  + (size_t)l*D*FFD; const __half* f2l = w_f2_l  + (size_t)l*D*FFD;
        const __half* g1h = w_g1_h  + (size_t)l*D3*D2; const __half* g1l = w_g1_l  + (size_t)l*D3*D2;
        const __half* g2h = w_g2_h  + (size_t)l*D3*D2; const __half* g2l = w_g2_l  + (size_t)l*D3*D2;
        const float* ob  = out_b + (size_t)l*D;
        const float* l2g = ln2_g + (size_t)l*D;  const float* l2b = ln2_b + (size_t)l*D;
        const float* fb1 = ff_b1 + (size_t)l*FFD;
        const float* fb2 = ff_b2 + (size_t)l*D;
        const float* gb1 = g1_bg + (size_t)l*D;
        const float* gb2 = g2_bg + (size_t)l*D;
        const float* ng = (l + 1 < LNUM) ? ln1_g + (size_t)(l+1)*D : on_g;
        const float* nb = (l + 1 < LNUM) ? ln1_b + (size_t)(l+1)*D : on_b;
        float* fout = (l + 1 < LNUM) ? nullptr : (float*)d_out;

        // join: layer-l weights must be split before use
        cudaStreamWaitEvent(0, evl[l], 0);

        // attention block
        gemm_mma<<<cD3, 256, SMEM_BYTES>>>(lhi, llo, D, qwh, qwl, nullptr, pqkv, 0, 0, D3, D, 0, gxD3, ntD3);
        attn_flash<<<dim3(TT/QTILE, BATCH*H), 256, ATTN_SMEM>>>(pqkv, phi, plo);
        gemm_mma<<<cD, 256, SMEM_BYTES>>>(phi, plo, D, owh, owl, ob, 0, chi + D, clo + D, D2, D, 2, gxD, ntD);
        gemm_mma<<<cD3, 256, SMEM_BYTES>>>(chi, clo, D2, g1h, g1l, nullptr, pgate, 0, 0, D3, D2, 0, gxD3, ntD3);
        gru_ln_split<<<NTOK, 256>>>(px, pgate, gb1, l2g, l2b, chi, clo, lhi, llo, nullptr);

        // feed-forward block
        gemm_mma<<<cFF, 256, SMEM_BYTES>>>(lhi, llo, D, f1h, f1l, fb1, 0, fhi, flo, FFD, D, 1, gxFF, ntFF);
        gemm_mma<<<cD, 256, SMEM_BYTES>>>(fhi, flo, FFD, f2h, f2l, fb2, 0, chi + D, clo + D, D2, FFD, 2, gxD, ntD);
        gemm_mma<<<cD3, 256, SMEM_BYTES>>>(chi, clo, D2, g2h, g2l, nullptr, pgate, 0, 0, D3, D2, 0, gxD3, ntD3);
        gru_ln_split<<<NTOK, 256>>>(px, pgate, gb2, ng, nb, chi, clo, lhi, llo, fout);
    }
    // streams/events intentionally not destroyed: kernel_launch only runs for
    // correctness + capture (graph replays don't re-enter), and destroying
    // capture-participating objects before EndCapture is unsafe.
}